// round 1
// baseline (speedup 1.0000x reference)
#include <cuda_runtime.h>

#define B_ 8
#define L_ 2048
#define C_ 256
#define D_ 32
#define NTOK (B_*L_)   // 16384

// -------- scratch (static device arrays: no allocation) --------
__device__ float g_ecg[NTOK*C_];
__device__ float g_pcg[NTOK*C_];
__device__ float g_q[4][NTOK*D_];
__device__ float g_k[4][NTOK*D_];
__device__ float g_v[4][NTOK*C_];
__device__ float g_o[2][NTOK*C_];   // intra-attention stash (per half)

// -------- split interleaved x[...,2] into two contiguous streams --------
__global__ void split_kernel(const float2* __restrict__ x2, int n) {
    int i = blockIdx.x*blockDim.x + threadIdx.x;
    int stride = gridDim.x*blockDim.x;
    for (; i < n; i += stride) {
        float2 v = x2[i];
        g_ecg[i] = v.x;
        g_pcg[i] = v.y;
    }
}

// -------- tiled projection GEMM: (64 rows x 32 cols)/CTA, K chunks of 64 --------
__global__ __launch_bounds__(256) void proj_kernel(const float* __restrict__ w,
        int src_sel, int kind, int idx) {
    __shared__ float s_x[64][68];   // padded: conflict-free broadcast reads
    __shared__ float s_w[64][36];   // padded: row base 144B -> float4 aligned
    const float* __restrict__ src = src_sel ? g_pcg : g_ecg;
    float* out; int dout;
    if (kind == 0)      { out = g_q[idx]; dout = D_; }
    else if (kind == 1) { out = g_k[idx]; dout = D_; }
    else                { out = g_v[idx]; dout = C_; }

    int t  = threadIdx.x;
    int b  = blockIdx.y;
    int R0 = blockIdx.x * 64;
    int dblk = blockIdx.z * 32;
    int tr = t >> 3;    // 0..31 -> rows tr, tr+32
    int tc = t & 7;     // 0..7  -> cols 4*tc..4*tc+3

    float a0[4] = {0.f,0.f,0.f,0.f}, a1[4] = {0.f,0.f,0.f,0.f};

    for (int kc = 0; kc < 4; kc++) {
        const float4* gx = (const float4*)src;
        #pragma unroll
        for (int i = 0; i < 4; i++) {
            int e = i*256 + t;          // 0..1023 over 64x16 float4
            int r = e >> 4, c4 = e & 15;
            float4 v = gx[(b*L_ + R0 + r)*(C_/4) + kc*16 + c4];
            *(float4*)&s_x[r][c4*4] = v;
        }
        #pragma unroll
        for (int i = 0; i < 8; i++) {
            int e = i*256 + t;          // 0..2047 over 64x32
            int kk = e >> 5, c = e & 31;
            s_w[kk][c] = w[(kc*64 + kk)*dout + dblk + c];
        }
        __syncthreads();
        #pragma unroll 8
        for (int kk = 0; kk < 64; kk++) {
            float x0 = s_x[tr][kk];
            float x1 = s_x[tr+32][kk];
            float4 wv = *(const float4*)&s_w[kk][tc*4];
            a0[0] += x0*wv.x; a0[1] += x0*wv.y; a0[2] += x0*wv.z; a0[3] += x0*wv.w;
            a1[0] += x1*wv.x; a1[1] += x1*wv.y; a1[2] += x1*wv.z; a1[3] += x1*wv.w;
        }
        __syncthreads();
    }
    int col = dblk + tc*4;
    int rg  = b*L_ + R0 + tr;
    *(float4*)&out[ rg      *dout + col] = make_float4(a0[0],a0[1],a0[2],a0[3]);
    *(float4*)&out[(rg + 32)*dout + col] = make_float4(a1[0],a1[1],a1[2],a1[3]);
}

// -------- packed fp32x2 FMA (Blackwell FFMA2, PTX-only) --------
union F4U { float4 f; unsigned long long u[2]; };
union F2U { float f[2]; unsigned long long u; };
__device__ __forceinline__ void fma2(unsigned long long& d,
                                     unsigned long long a, unsigned long long b) {
    asm("fma.rn.f32x2 %0, %1, %2, %0;" : "+l"(d) : "l"(a), "l"(b));
}

#define SMEM_Q_F4 512    // 64 x 8 float4
#define SMEM_K_F4 576    // 64 x 9 float4 (padded)
#define SMEM_V_F4 4096   // 64 x 64 float4
#define ATTN_SMEM ((SMEM_Q_F4 + SMEM_K_F4 + SMEM_V_F4)*16 + 8*8*64*4)  // 99328 B

// Merged attention: blockIdx.z = half (0: ecg out, 1: pcg out).
// pass 0 = intra attention (stash normalized to g_o[h]),
// pass 1 = inter attention, fused out = inter + coef*intra.
__global__ __launch_bounds__(256, 2) void attn_kernel(float* __restrict__ dst,
        const float* __restrict__ alpha, const float* __restrict__ gamma) {
    extern __shared__ float4 smem4[];
    float4* sQ = smem4;                 // [64][8]
    float4* sK = sQ + SMEM_Q_F4;        // [64][9] padded
    float4* sV = sK + SMEM_K_F4;        // [64][64]
    float*  sS = (float*)(sV + SMEM_V_F4);  // [8 warps][8 rows][64 keys]

    int t = threadIdx.x;
    int w = t >> 5;
    int l = t & 31;
    int b = blockIdx.y;
    int h = blockIdx.z;
    int R0 = blockIdx.x * 64;
    int tokbase = b * L_;

    int idx_a = h ? 2 : 0;            // intra
    int idx_b = h ? 3 : 1;            // inter
    const float* coefp = h ? gamma : alpha;
    int ooff = h * 256;

    float* sSw = sS + w*8*64;
    const float SC = 0.17677669529663687f;  // 1/sqrt(32)

    for (int pass = 0; pass < 2; pass++) {
        int idx = (pass == 0) ? idx_a : idx_b;
        const float* __restrict__ Q = g_q[idx];
        const float* __restrict__ K = g_k[idx];
        const float* __restrict__ V = g_v[idx];

        __syncthreads();   // protect sQ across passes
        {
            const float4* gq = (const float4*)Q;
            #pragma unroll
            for (int i = 0; i < 2; i++) {
                int e = i*256 + t;     // 0..511 over 64x8
                int r = e >> 3, dd = e & 7;
                sQ[r*8 + dd] = gq[(tokbase + R0 + r)*8 + dd];
            }
        }

        unsigned long long acc0[8][2], acc1[8][2];
        float lsum[8];
        #pragma unroll
        for (int r = 0; r < 8; r++) {
            acc0[r][0]=acc0[r][1]=acc1[r][0]=acc1[r][1]=0ull;
            lsum[r] = 0.f;
        }

        for (int kt = 0; kt < L_/64; kt++) {
            __syncthreads();
            const float4* gk = (const float4*)K;
            #pragma unroll
            for (int i = 0; i < 2; i++) {
                int e = i*256 + t;
                int j = e >> 3, dd = e & 7;
                sK[j*9 + dd] = gk[(tokbase + kt*64 + j)*8 + dd];
            }
            const float4* gv = (const float4*)V;
            #pragma unroll
            for (int i = 0; i < 16; i++) {
                int e = i*256 + t;     // 0..4095 over 64x64
                int j = e >> 6, c = e & 63;
                sV[j*64 + c] = gv[(tokbase + kt*64 + j)*64 + c];
            }
            __syncthreads();

            // ---- scores: lane handles keys l and l+32 for its warp's 8 rows ----
            float s0[8], s1[8];
            #pragma unroll
            for (int r = 0; r < 8; r++) { s0[r]=0.f; s1[r]=0.f; }
            #pragma unroll
            for (int dd = 0; dd < 8; dd++) {
                float4 k0 = sK[ l     *9 + dd];
                float4 k1 = sK[(l+32) *9 + dd];
                #pragma unroll
                for (int r = 0; r < 8; r++) {
                    float4 q = sQ[(w*8 + r)*8 + dd];
                    s0[r] += q.x*k0.x + q.y*k0.y + q.z*k0.z + q.w*k0.w;
                    s1[r] += q.x*k1.x + q.y*k1.y + q.z*k1.z + q.w*k1.w;
                }
            }
            #pragma unroll
            for (int r = 0; r < 8; r++) {
                float p0 = __expf(s0[r]*SC);
                float p1 = __expf(s1[r]*SC);
                sSw[r*64 + l]      = p0;
                sSw[r*64 + l + 32] = p1;
                lsum[r] += p0 + p1;
            }
            __syncwarp();

            // ---- P*V: lane owns d in {4l..4l+3} and {128+4l..128+4l+3} ----
            #pragma unroll 2
            for (int j = 0; j < 64; j++) {
                F4U v0, v1;
                v0.f = sV[j*64 + l];
                v1.f = sV[j*64 + 32 + l];
                #pragma unroll
                for (int r = 0; r < 8; r++) {
                    F2U p2; p2.f[0] = p2.f[1] = sSw[r*64 + j];
                    fma2(acc0[r][0], p2.u, v0.u[0]);
                    fma2(acc0[r][1], p2.u, v0.u[1]);
                    fma2(acc1[r][0], p2.u, v1.u[0]);
                    fma2(acc1[r][1], p2.u, v1.u[1]);
                }
            }
            __syncwarp();
        }

        // ---- reduce softmax denominators across the warp ----
        #pragma unroll
        for (int r = 0; r < 8; r++) {
            float v = lsum[r];
            v += __shfl_xor_sync(0xffffffffu, v, 16);
            v += __shfl_xor_sync(0xffffffffu, v, 8);
            v += __shfl_xor_sync(0xffffffffu, v, 4);
            v += __shfl_xor_sync(0xffffffffu, v, 2);
            v += __shfl_xor_sync(0xffffffffu, v, 1);
            lsum[r] = 1.0f / v;
        }

        if (pass == 0) {
            // stash normalized intra result; each thread will read back its own values
            float* st = g_o[h];
            #pragma unroll
            for (int r = 0; r < 8; r++) {
                int row = tokbase + R0 + w*8 + r;
                float inv = lsum[r];
                F2U t0; F4U o0, o1;
                t0.u = acc0[r][0]; o0.f.x = t0.f[0]*inv; o0.f.y = t0.f[1]*inv;
                t0.u = acc0[r][1]; o0.f.z = t0.f[0]*inv; o0.f.w = t0.f[1]*inv;
                t0.u = acc1[r][0]; o1.f.x = t0.f[0]*inv; o1.f.y = t0.f[1]*inv;
                t0.u = acc1[r][1]; o1.f.z = t0.f[0]*inv; o1.f.w = t0.f[1]*inv;
                *(float4*)&st[row*256 + 4*l]       = o0.f;
                *(float4*)&st[row*256 + 128 + 4*l] = o1.f;
            }
        } else {
            float a = coefp[0];
            const float4* pv = (const float4*)g_o[h];
            #pragma unroll
            for (int r = 0; r < 8; r++) {
                int row = tokbase + R0 + w*8 + r;
                float inv = lsum[r];
                F2U t0; F4U o0, o1;
                t0.u = acc0[r][0]; o0.f.x = t0.f[0]*inv; o0.f.y = t0.f[1]*inv;
                t0.u = acc0[r][1]; o0.f.z = t0.f[0]*inv; o0.f.w = t0.f[1]*inv;
                t0.u = acc1[r][0]; o1.f.x = t0.f[0]*inv; o1.f.y = t0.f[1]*inv;
                t0.u = acc1[r][1]; o1.f.z = t0.f[0]*inv; o1.f.w = t0.f[1]*inv;
                float4 p0 = pv[row*64 + l];
                float4 p1 = pv[row*64 + 32 + l];
                o0.f.x += a*p0.x; o0.f.y += a*p0.y; o0.f.z += a*p0.z; o0.f.w += a*p0.w;
                o1.f.x += a*p1.x; o1.f.y += a*p1.y; o1.f.z += a*p1.z; o1.f.w += a*p1.w;
                *(float4*)&dst[row*512 + ooff + 4*l]       = o0.f;
                *(float4*)&dst[row*512 + ooff + 128 + 4*l] = o1.f;
            }
        }
    }
}

extern "C" void kernel_launch(void* const* d_in, const int* in_sizes, int n_in,
                              void* d_out, int out_size) {
    const float* x = (const float*)d_in[0];
    const float* wt[12];
    for (int i = 0; i < 12; i++) wt[i] = (const float*)d_in[1+i];
    const float* alpha = (const float*)d_in[13];
    const float* gamma = (const float*)d_in[14];
    float* out = (float*)d_out;

    split_kernel<<<2048, 256>>>((const float2*)x, NTOK*C_);

    dim3 pgD(L_/64, B_, 1);   // dout = 32
    dim3 pgC(L_/64, B_, 8);   // dout = 256
    // attn 0 (ecg intra):  q=ecg*w1, k=ecg*w2, v=ecg*w3
    proj_kernel<<<pgD,256>>>(wt[0],  0, 0, 0);
    proj_kernel<<<pgD,256>>>(wt[1],  0, 1, 0);
    proj_kernel<<<pgC,256>>>(wt[2],  0, 2, 0);
    // attn 1 (ecg inter):  q=ecg*w4, k=pcg*w5, v=pcg*w6
    proj_kernel<<<pgD,256>>>(wt[3],  0, 0, 1);
    proj_kernel<<<pgD,256>>>(wt[4],  1, 1, 1);
    proj_kernel<<<pgC,256>>>(wt[5],  1, 2, 1);
    // attn 2 (pcg intra):  q=pcg*w7, k=pcg*w8, v=pcg*w9
    proj_kernel<<<pgD,256>>>(wt[6],  1, 0, 2);
    proj_kernel<<<pgD,256>>>(wt[7],  1, 1, 2);
    proj_kernel<<<pgC,256>>>(wt[8],  1, 2, 2);
    // attn 3 (pcg inter):  q=pcg*w10, k=ecg*w11, v=ecg*w12
    proj_kernel<<<pgD,256>>>(wt[9],  1, 0, 3);
    proj_kernel<<<pgD,256>>>(wt[10], 0, 1, 3);
    proj_kernel<<<pgC,256>>>(wt[11], 0, 2, 3);

    cudaFuncSetAttribute(attn_kernel,
                         cudaFuncAttributeMaxDynamicSharedMemorySize, ATTN_SMEM);
    dim3 ag(L_/64, B_, 2);
    attn_kernel<<<ag, 256, ATTN_SMEM>>>(out, alpha, gamma);
}

// round 3
// speedup vs baseline: 1.3548x; 1.3548x over previous
#include <cuda_runtime.h>
#include <stdint.h>

#define B_ 8
#define L_ 2048
#define C_ 256
#define D_ 32
#define NTOK (B_*L_)   // 16384

// -------- scratch (static device arrays: no allocation) --------
__device__ float g_ecg[NTOK*C_];
__device__ float g_pcg[NTOK*C_];
__device__ float g_q[4][NTOK*D_];
__device__ float g_k[4][NTOK*D_];
__device__ float g_v[4][NTOK*C_];
__device__ float g_o[2][NTOK*C_];   // intra-attention stash (per half)

// -------- tf32 helpers --------
__device__ __forceinline__ uint32_t f2tf(float x) {
    uint32_t u;
    asm("cvt.rna.tf32.f32 %0, %1;" : "=r"(u) : "f"(x));
    return u;
}
__device__ __forceinline__ void hilo(float x, uint32_t& h, uint32_t& l) {
    h = f2tf(x);
    l = f2tf(x - __uint_as_float(h));
}
__device__ __forceinline__ void mma8(float* d, const uint32_t* a,
                                     uint32_t b0, uint32_t b1) {
    asm volatile(
        "mma.sync.aligned.m16n8k8.row.col.f32.tf32.tf32.f32 "
        "{%0,%1,%2,%3}, {%4,%5,%6,%7}, {%8,%9}, {%0,%1,%2,%3};"
        : "+f"(d[0]), "+f"(d[1]), "+f"(d[2]), "+f"(d[3])
        : "r"(a[0]), "r"(a[1]), "r"(a[2]), "r"(a[3]), "r"(b0), "r"(b1));
}

// -------- split interleaved x[...,2] into two contiguous streams --------
__global__ void split_kernel(const float2* __restrict__ x2, int n) {
    int i = blockIdx.x*blockDim.x + threadIdx.x;
    int stride = gridDim.x*blockDim.x;
    for (; i < n; i += stride) {
        float2 v = x2[i];
        g_ecg[i] = v.x;
        g_pcg[i] = v.y;
    }
}

// ============ 3xTF32 projection GEMM ============
// C[M,N] = X[M,256] * W[256,N].  CTA: 128 rows x NT*8 cols, 8 warps (16 rows each).
#define PX 36              // sX row stride (u32): 4 mod 32 -> conflict-free A frags
template<int NT, int PW>   // PW must be == 8 mod 32
__global__ __launch_bounds__(256) void proj_mma(const float* __restrict__ w,
        int src_sel, int kind, int idx) {
    extern __shared__ uint32_t ps[];
    uint32_t* sXh = ps;
    uint32_t* sXl = ps + 128*PX;
    uint32_t* sWh = ps + 2*128*PX;
    uint32_t* sWl = sWh + 32*PW;

    const float* __restrict__ src = src_sel ? g_pcg : g_ecg;
    float* out; int N;
    if (kind == 0)      { out = g_q[idx]; N = D_; }
    else if (kind == 1) { out = g_k[idx]; N = D_; }
    else                { out = g_v[idx]; N = C_; }

    int t = threadIdx.x;
    int wp = t >> 5, lane = t & 31;
    int g = lane >> 2, t4 = lane & 3;
    int row0 = blockIdx.x * 128;
    int col0 = blockIdx.y * (NT*8);

    float acc[NT][4];
    #pragma unroll
    for (int n = 0; n < NT; n++) { acc[n][0]=acc[n][1]=acc[n][2]=acc[n][3]=0.f; }

    for (int kc = 0; kc < 8; kc++) {
        __syncthreads();
        // X chunk 128x32 -> hi/lo tf32 smem
        {
            const float4* gx = (const float4*)src;
            #pragma unroll
            for (int i = 0; i < 4; i++) {
                int e = i*256 + t;             // 0..1023 over 128x8 f4
                int r = e >> 3, c4 = e & 7;
                float4 v = gx[(row0 + r)*(C_/4) + kc*8 + c4];
                uint4 hu, lu;
                hilo(v.x, hu.x, lu.x); hilo(v.y, hu.y, lu.y);
                hilo(v.z, hu.z, lu.z); hilo(v.w, hu.w, lu.w);
                *(uint4*)&sXh[r*PX + c4*4] = hu;
                *(uint4*)&sXl[r*PX + c4*4] = lu;
            }
        }
        // W chunk 32 x NT*8 -> hi/lo tf32 smem
        {
            const float4* gw = (const float4*)w;
            #pragma unroll
            for (int i = 0; i < NT/4; i++) {
                int e = i*256 + t;             // over 32*(NT*2) f4
                int k = e / (NT*2), c4 = e % (NT*2);
                float4 v = gw[((kc*32 + k)*N + col0)/4 + c4];
                uint4 hu, lu;
                hilo(v.x, hu.x, lu.x); hilo(v.y, hu.y, lu.y);
                hilo(v.z, hu.z, lu.z); hilo(v.w, hu.w, lu.w);
                *(uint4*)&sWh[k*PW + c4*4] = hu;
                *(uint4*)&sWl[k*PW + c4*4] = lu;
            }
        }
        __syncthreads();
        #pragma unroll
        for (int kk = 0; kk < 4; kk++) {
            uint32_t ah[4], al[4];
            ah[0] = sXh[(wp*16 + g    )*PX + kk*8 + t4];
            ah[1] = sXh[(wp*16 + g + 8)*PX + kk*8 + t4];
            ah[2] = sXh[(wp*16 + g    )*PX + kk*8 + t4 + 4];
            ah[3] = sXh[(wp*16 + g + 8)*PX + kk*8 + t4 + 4];
            al[0] = sXl[(wp*16 + g    )*PX + kk*8 + t4];
            al[1] = sXl[(wp*16 + g + 8)*PX + kk*8 + t4];
            al[2] = sXl[(wp*16 + g    )*PX + kk*8 + t4 + 4];
            al[3] = sXl[(wp*16 + g + 8)*PX + kk*8 + t4 + 4];
            #pragma unroll
            for (int n = 0; n < NT; n++) {
                uint32_t bh0 = sWh[(kk*8 + t4    )*PW + n*8 + g];
                uint32_t bh1 = sWh[(kk*8 + t4 + 4)*PW + n*8 + g];
                uint32_t bl0 = sWl[(kk*8 + t4    )*PW + n*8 + g];
                uint32_t bl1 = sWl[(kk*8 + t4 + 4)*PW + n*8 + g];
                mma8(acc[n], al, bh0, bh1);
                mma8(acc[n], ah, bl0, bl1);
                mma8(acc[n], ah, bh0, bh1);
            }
        }
    }
    int r0 = row0 + wp*16 + g;
    #pragma unroll
    for (int n = 0; n < NT; n++) {
        int col = col0 + n*8 + 2*t4;
        *(float2*)&out[ r0     *N + col] = make_float2(acc[n][0], acc[n][1]);
        *(float2*)&out[(r0 + 8)*N + col] = make_float2(acc[n][2], acc[n][3]);
    }
}

// ============ tf32 flash attention (two fused passes) ============
// CTA: 64 query rows, 512 threads = 16 warps.
// warp: rg = wp>>2 (16-row group, 4 groups = 64 rows),
//       ch = wp&3  (8-key score group / 64-col output quarter).
#define ROWS 64
#define KT   32
#define PQ   36    // 4 mod 32
#define PK   36
#define PV   264   // 8 mod 32
#define PP   36
#define OFF_QH 0
#define OFF_QL (OFF_QH + 64*PQ)           // 2304
#define OFF_KH (OFF_QL + 64*PQ)           // 4608
#define OFF_KL (OFF_KH + 32*PK)           // 5760
#define OFF_V  (OFF_KL + 32*PK)           // 6912
#define OFF_P  (OFF_V + 32*PV)            // 15360
#define OFF_S  (OFF_P + 64*PP)            // 17664
#define SMEM_U32 (OFF_S + 16*16)          // 17920
#define ATTN_SMEM (SMEM_U32*4)            // 71680 B

__global__ __launch_bounds__(512, 1) void attn_mma(float* __restrict__ dst,
        const float* __restrict__ alpha, const float* __restrict__ gamma) {
    extern __shared__ uint32_t sm[];
    uint32_t* sQh = sm + OFF_QH;
    uint32_t* sQl = sm + OFF_QL;
    uint32_t* sKh = sm + OFF_KH;
    uint32_t* sKl = sm + OFF_KL;
    uint32_t* sV  = sm + OFF_V;
    uint32_t* sP  = sm + OFF_P;
    float*    sS  = (float*)(sm + OFF_S);

    int t = threadIdx.x;
    int wp = t >> 5, lane = t & 31;
    int g = lane >> 2, t4 = lane & 3;
    int rg = wp >> 2, ch = wp & 3;
    int b = blockIdx.y, h = blockIdx.z;
    int row0 = blockIdx.x * ROWS;
    int tokbase = b * L_;

    int idx_a = h ? 2 : 0;
    int idx_b = h ? 3 : 1;
    const float* coefp = h ? gamma : alpha;
    const float SC = 0.17677669529663687f;  // 1/sqrt(32)

    for (int pass = 0; pass < 2; pass++) {
        int idx = (pass == 0) ? idx_a : idx_b;
        const float* __restrict__ Q = g_q[idx];
        const float* __restrict__ K = g_k[idx];
        const float* __restrict__ V = g_v[idx];

        __syncthreads();
        // stage Q (64x32) hi/lo
        {
            const float4* gq = (const float4*)Q;
            int r = t >> 3, c4 = t & 7;      // 512 threads = 64x8 f4 exactly
            float4 v = gq[(tokbase + row0 + r)*8 + c4];
            uint4 hu, lu;
            hilo(v.x, hu.x, lu.x); hilo(v.y, hu.y, lu.y);
            hilo(v.z, hu.z, lu.z); hilo(v.w, hu.w, lu.w);
            *(uint4*)&sQh[r*PQ + c4*4] = hu;
            *(uint4*)&sQl[r*PQ + c4*4] = lu;
        }
        __syncthreads();
        // hoist Q fragments for this warp's 16 rows (reused all key tiles)
        uint32_t qh[4][4], ql[4][4];
        #pragma unroll
        for (int kk = 0; kk < 4; kk++) {
            qh[kk][0] = sQh[(rg*16 + g    )*PQ + kk*8 + t4];
            qh[kk][1] = sQh[(rg*16 + g + 8)*PQ + kk*8 + t4];
            qh[kk][2] = sQh[(rg*16 + g    )*PQ + kk*8 + t4 + 4];
            qh[kk][3] = sQh[(rg*16 + g + 8)*PQ + kk*8 + t4 + 4];
            ql[kk][0] = sQl[(rg*16 + g    )*PQ + kk*8 + t4];
            ql[kk][1] = sQl[(rg*16 + g + 8)*PQ + kk*8 + t4];
            ql[kk][2] = sQl[(rg*16 + g    )*PQ + kk*8 + t4 + 4];
            ql[kk][3] = sQl[(rg*16 + g + 8)*PQ + kk*8 + t4 + 4];
        }

        float acc[8][4];
        #pragma unroll
        for (int n = 0; n < 8; n++) { acc[n][0]=acc[n][1]=acc[n][2]=acc[n][3]=0.f; }
        float rs0 = 0.f, rs1 = 0.f;

        for (int kt = 0; kt < L_/KT; kt++) {
            __syncthreads();
            // stage K tile (32x32) hi/lo
            if (t < 256) {
                int r = t >> 3, c4 = t & 7;
                float4 v = ((const float4*)K)[(tokbase + kt*KT + r)*8 + c4];
                uint4 hu, lu;
                hilo(v.x, hu.x, lu.x); hilo(v.y, hu.y, lu.y);
                hilo(v.z, hu.z, lu.z); hilo(v.w, hu.w, lu.w);
                *(uint4*)&sKh[r*PK + c4*4] = hu;
                *(uint4*)&sKl[r*PK + c4*4] = lu;
            }
            // stage V tile (32x256) single tf32
            {
                const float4* gv = (const float4*)V;
                #pragma unroll
                for (int i = 0; i < 4; i++) {
                    int e = i*512 + t;        // 0..2047 over 32x64 f4
                    int r = e >> 6, c4 = e & 63;
                    float4 v = gv[(tokbase + kt*KT + r)*64 + c4];
                    uint4 u = make_uint4(f2tf(v.x), f2tf(v.y), f2tf(v.z), f2tf(v.w));
                    *(uint4*)&sV[r*PV + c4*4] = u;
                }
            }
            __syncthreads();

            // ---- scores (3xTF32): warp's 16 rows x 8 keys (ch group) ----
            float s[4] = {0.f, 0.f, 0.f, 0.f};
            #pragma unroll
            for (int kk = 0; kk < 4; kk++) {
                uint32_t bh0 = sKh[(ch*8 + g)*PK + kk*8 + t4];
                uint32_t bh1 = sKh[(ch*8 + g)*PK + kk*8 + t4 + 4];
                uint32_t bl0 = sKl[(ch*8 + g)*PK + kk*8 + t4];
                uint32_t bl1 = sKl[(ch*8 + g)*PK + kk*8 + t4 + 4];
                mma8(s, ql[kk], bh0, bh1);
                mma8(s, qh[kk], bl0, bl1);
                mma8(s, qh[kk], bh0, bh1);
            }
            float p0 = __expf(s[0]*SC);
            float p1 = __expf(s[1]*SC);
            float p2 = __expf(s[2]*SC);
            float p3 = __expf(s[3]*SC);
            rs0 += p0 + p1;
            rs1 += p2 + p3;
            *(uint2*)&sP[(rg*16 + g    )*PP + ch*8 + 2*t4] = make_uint2(f2tf(p0), f2tf(p1));
            *(uint2*)&sP[(rg*16 + g + 8)*PP + ch*8 + 2*t4] = make_uint2(f2tf(p2), f2tf(p3));
            __syncthreads();

            // ---- P*V: warp's 16 rows x 64 cols (ch quarter) ----
            #pragma unroll
            for (int kk = 0; kk < 4; kk++) {
                uint32_t a[4];
                a[0] = sP[(rg*16 + g    )*PP + kk*8 + t4];
                a[1] = sP[(rg*16 + g + 8)*PP + kk*8 + t4];
                a[2] = sP[(rg*16 + g    )*PP + kk*8 + t4 + 4];
                a[3] = sP[(rg*16 + g + 8)*PP + kk*8 + t4 + 4];
                #pragma unroll
                for (int n = 0; n < 8; n++) {
                    int col = ch*64 + n*8 + g;
                    uint32_t b0 = sV[(kk*8 + t4    )*PV + col];
                    uint32_t b1 = sV[(kk*8 + t4 + 4)*PV + col];
                    mma8(acc[n], a, b0, b1);
                }
            }
        }

        // ---- softmax denominators ----
        rs0 += __shfl_xor_sync(0xffffffffu, rs0, 1);
        rs0 += __shfl_xor_sync(0xffffffffu, rs0, 2);
        rs1 += __shfl_xor_sync(0xffffffffu, rs1, 1);
        rs1 += __shfl_xor_sync(0xffffffffu, rs1, 2);
        if (t4 == 0) {
            sS[(rg*4 + ch)*16 + g    ] = rs0;
            sS[(rg*4 + ch)*16 + g + 8] = rs1;
        }
        __syncthreads();
        float den0 = 0.f, den1 = 0.f;
        #pragma unroll
        for (int c = 0; c < 4; c++) {
            den0 += sS[(rg*4 + c)*16 + g    ];
            den1 += sS[(rg*4 + c)*16 + g + 8];
        }
        float inv0 = 1.0f / den0;
        float inv1 = 1.0f / den1;

        int r0 = tokbase + row0 + rg*16 + g;
        if (pass == 0) {
            float* st = g_o[h];
            #pragma unroll
            for (int n = 0; n < 8; n++) {
                int col = ch*64 + n*8 + 2*t4;
                *(float2*)&st[ r0     *256 + col] = make_float2(acc[n][0]*inv0, acc[n][1]*inv0);
                *(float2*)&st[(r0 + 8)*256 + col] = make_float2(acc[n][2]*inv1, acc[n][3]*inv1);
            }
        } else {
            float cf = coefp[0];
            const float* st = g_o[h];
            int ooff = h * 256;
            #pragma unroll
            for (int n = 0; n < 8; n++) {
                int col = ch*64 + n*8 + 2*t4;
                float2 s0 = *(const float2*)&st[ r0     *256 + col];
                float2 s1 = *(const float2*)&st[(r0 + 8)*256 + col];
                float2 o0 = make_float2(acc[n][0]*inv0 + cf*s0.x,
                                        acc[n][1]*inv0 + cf*s0.y);
                float2 o1 = make_float2(acc[n][2]*inv1 + cf*s1.x,
                                        acc[n][3]*inv1 + cf*s1.y);
                *(float2*)&dst[ r0     *512 + ooff + col] = o0;
                *(float2*)&dst[(r0 + 8)*512 + ooff + col] = o1;
            }
        }
    }
}

extern "C" void kernel_launch(void* const* d_in, const int* in_sizes, int n_in,
                              void* d_out, int out_size) {
    const float* x = (const float*)d_in[0];
    const float* wt[12];
    for (int i = 0; i < 12; i++) wt[i] = (const float*)d_in[1+i];
    const float* alpha = (const float*)d_in[13];
    const float* gamma = (const float*)d_in[14];
    float* out = (float*)d_out;

    const int SM_D = (2*128*PX + 2*32*40)*4;   // 47104 B
    const int SM_C = (2*128*PX + 2*32*72)*4;   // 55296 B
    cudaFuncSetAttribute(proj_mma<4,40>,
                         cudaFuncAttributeMaxDynamicSharedMemorySize, SM_D);
    cudaFuncSetAttribute(proj_mma<8,72>,
                         cudaFuncAttributeMaxDynamicSharedMemorySize, SM_C);
    cudaFuncSetAttribute(attn_mma,
                         cudaFuncAttributeMaxDynamicSharedMemorySize, ATTN_SMEM);

    split_kernel<<<2048, 256>>>((const float2*)x, NTOK*C_);

    dim3 gD(NTOK/128, 1);   // N=32
    dim3 gC(NTOK/128, 4);   // N=256
    // attn 0 (ecg intra):  q=ecg*w1, k=ecg*w2, v=ecg*w3
    proj_mma<4,40><<<gD,256,SM_D>>>(wt[0],  0, 0, 0);
    proj_mma<4,40><<<gD,256,SM_D>>>(wt[1],  0, 1, 0);
    proj_mma<8,72><<<gC,256,SM_C>>>(wt[2],  0, 2, 0);
    // attn 1 (ecg inter):  q=ecg*w4, k=pcg*w5, v=pcg*w6
    proj_mma<4,40><<<gD,256,SM_D>>>(wt[3],  0, 0, 1);
    proj_mma<4,40><<<gD,256,SM_D>>>(wt[4],  1, 1, 1);
    proj_mma<8,72><<<gC,256,SM_C>>>(wt[5],  1, 2, 1);
    // attn 2 (pcg intra):  q=pcg*w7, k=pcg*w8, v=pcg*w9
    proj_mma<4,40><<<gD,256,SM_D>>>(wt[6],  1, 0, 2);
    proj_mma<4,40><<<gD,256,SM_D>>>(wt[7],  1, 1, 2);
    proj_mma<8,72><<<gC,256,SM_C>>>(wt[8],  1, 2, 2);
    // attn 3 (pcg inter):  q=pcg*w10, k=ecg*w11, v=ecg*w12
    proj_mma<4,40><<<gD,256,SM_D>>>(wt[9],  1, 0, 3);
    proj_mma<4,40><<<gD,256,SM_D>>>(wt[10], 0, 1, 3);
    proj_mma<8,72><<<gC,256,SM_C>>>(wt[11], 0, 2, 3);

    dim3 ag(L_/ROWS, B_, 2);
    attn_mma<<<ag, 512, ATTN_SMEM>>>(out, alpha, gamma);
}

// round 4
// speedup vs baseline: 2.2554x; 1.6647x over previous
#include <cuda_runtime.h>
#include <stdint.h>

#define B_ 8
#define L_ 2048
#define C_ 256
#define D_ 32
#define NTOK (B_*L_)   // 16384

// -------- scratch (static device arrays: no allocation) --------
__device__ float g_ecg[NTOK*C_];
__device__ float g_pcg[NTOK*C_];
__device__ float g_q[4][NTOK*D_];
__device__ float g_k[4][NTOK*D_];
__device__ float g_v[4][NTOK*C_];
__device__ float g_o[2][NTOK*C_];   // intra-attention stash (per half)

// -------- helpers --------
__device__ __forceinline__ uint32_t f2tf(float x) {
    uint32_t u;
    asm("cvt.rna.tf32.f32 %0, %1;" : "=r"(u) : "f"(x));
    return u;
}
__device__ __forceinline__ void mma8(float* d, const uint32_t* a,
                                     uint32_t b0, uint32_t b1) {
    asm volatile(
        "mma.sync.aligned.m16n8k8.row.col.f32.tf32.tf32.f32 "
        "{%0,%1,%2,%3}, {%4,%5,%6,%7}, {%8,%9}, {%0,%1,%2,%3};"
        : "+f"(d[0]), "+f"(d[1]), "+f"(d[2]), "+f"(d[3])
        : "r"(a[0]), "r"(a[1]), "r"(a[2]), "r"(a[3]), "r"(b0), "r"(b1));
}
__device__ __forceinline__ void cp16(uint32_t dst, const void* src) {
    asm volatile("cp.async.cg.shared.global [%0], [%1], 16;" :: "r"(dst), "l"(src));
}
#define CP_COMMIT() asm volatile("cp.async.commit_group;")
#define CP_WAIT0()  asm volatile("cp.async.wait_group 0;")

// -------- split interleaved x[...,2] into two contiguous streams --------
__global__ void split_kernel(const float2* __restrict__ x2, int n) {
    int i = blockIdx.x*blockDim.x + threadIdx.x;
    int stride = gridDim.x*blockDim.x;
    for (; i < n; i += stride) {
        float2 v = x2[i];
        g_ecg[i] = v.x;
        g_pcg[i] = v.y;
    }
}

// ============ 3xTF32 projection GEMMs (raw staging + cp.async) ============
// CTA tile: 128 rows x 64 cols, 256 threads (8 warps, 16 rows each), kc = 8 chunks of 32.
#define PX 36   // 4 mod 32
#define PW 72   // 8 mod 32
#define PROJ_SMEM ((2*128*PX + 2*32*PW)*4)   // 55296 B

struct QKArgs { const float* wa[4]; const float* wb[4]; };
struct VArgs  { const float* wv[4]; };

__device__ __forceinline__ void proj_core(uint32_t sb, const float* sm_f,
        const float* X, int row0, float* outp[8], int outN[8], int outc[8]) {
    int t = threadIdx.x;
    int wp = t >> 5, lane = t & 31;
    int g = lane >> 2, t4 = lane & 3;
    const uint32_t* smu = (const uint32_t*)sm_f;

    float acc[8][4];
    #pragma unroll
    for (int n = 0; n < 8; n++) { acc[n][0]=acc[n][1]=acc[n][2]=acc[n][3]=0.f; }

    for (int kc = 0; kc < 8; kc++) {
        CP_WAIT0();
        __syncthreads();
        // compute uses buf = kc&1 (already resident); caller prefetches kc+1.
        // (prefetch issued by caller via callback-free inline below)
        int buf = kc & 1;
        const float* sX = sm_f + buf*128*PX;
        const float* sW = sm_f + 2*128*PX + buf*32*PW;
        // prefetch next chunk
        // NOTE: handled in the caller kernels (they know src pointers)
        // -- this function body only does the mma math; see kernels.
        (void)sX; (void)sW; (void)smu; (void)sb; (void)X; (void)row0;
        (void)outp; (void)outN; (void)outc;
        break;
    }
}

// ---- fused Q/K pair projection: y in 0..3, each CTA does 128 rows x 64 cols ----
__global__ __launch_bounds__(256, 4) void proj_qk(QKArgs args) {
    extern __shared__ float smf[];
    uint32_t sb;
    { uint64_t a = __cvta_generic_to_shared(smf); sb = (uint32_t)a; }
    int t = threadIdx.x;
    int wp = t >> 5, lane = t & 31;
    int g = lane >> 2, t4 = lane & 3;
    int row0 = blockIdx.x * 128;
    int y = blockIdx.y;

    const float* wa = args.wa[y];
    const float* wb = args.wb[y];
    const float* X  = (y < 2) ? g_ecg : g_pcg;
    float* oa = (y==0) ? g_q[0] : (y==1) ? g_q[1] : (y==2) ? g_q[2] : g_k[2];
    float* ob = (y==0) ? g_k[0] : (y==1) ? g_k[3] : (y==2) ? g_k[1] : g_q[3];

    // prefetch chunk 0
    #pragma unroll
    for (int i = 0; i < 4; i++) {
        int e = i*256 + t; int r = e >> 3, c4 = e & 7;
        cp16(sb + (r*PX + c4*4)*4, X + (row0 + r)*C_ + c4*4);
    }
    #pragma unroll
    for (int i = 0; i < 2; i++) {
        int e = i*256 + t; int k = e >> 4, c4 = e & 15;
        const float* src = (c4 < 8) ? (wa + k*D_ + c4*4) : (wb + k*D_ + (c4-8)*4);
        cp16(sb + (2*128*PX + k*PW + c4*4)*4, src);
    }
    CP_COMMIT();

    float acc[8][4];
    #pragma unroll
    for (int n = 0; n < 8; n++) { acc[n][0]=acc[n][1]=acc[n][2]=acc[n][3]=0.f; }

    for (int kc = 0; kc < 8; kc++) {
        CP_WAIT0();
        __syncthreads();
        int buf = kc & 1, nbuf = buf ^ 1;
        if (kc < 7) {
            #pragma unroll
            for (int i = 0; i < 4; i++) {
                int e = i*256 + t; int r = e >> 3, c4 = e & 7;
                cp16(sb + (nbuf*128*PX + r*PX + c4*4)*4,
                     X + (row0 + r)*C_ + (kc+1)*32 + c4*4);
            }
            #pragma unroll
            for (int i = 0; i < 2; i++) {
                int e = i*256 + t; int k = e >> 4, c4 = e & 15;
                int krow = (kc+1)*32 + k;
                const float* src = (c4 < 8) ? (wa + krow*D_ + c4*4)
                                            : (wb + krow*D_ + (c4-8)*4);
                cp16(sb + (2*128*PX + nbuf*32*PW + k*PW + c4*4)*4, src);
            }
            CP_COMMIT();
        }
        const float* sX = smf + buf*128*PX;
        const float* sW = smf + 2*128*PX + buf*32*PW;
        #pragma unroll
        for (int kk = 0; kk < 4; kk++) {
            float ar[4];
            ar[0] = sX[(wp*16 + g    )*PX + kk*8 + t4];
            ar[1] = sX[(wp*16 + g + 8)*PX + kk*8 + t4];
            ar[2] = sX[(wp*16 + g    )*PX + kk*8 + t4 + 4];
            ar[3] = sX[(wp*16 + g + 8)*PX + kk*8 + t4 + 4];
            uint32_t ah[4], al[4];
            #pragma unroll
            for (int i = 0; i < 4; i++) {
                ah[i] = f2tf(ar[i]);
                al[i] = __float_as_uint(ar[i] - __uint_as_float(ah[i]));
            }
            #pragma unroll
            for (int n = 0; n < 8; n++) {
                float br0 = sW[(kk*8 + t4    )*PW + n*8 + g];
                float br1 = sW[(kk*8 + t4 + 4)*PW + n*8 + g];
                uint32_t bh0 = f2tf(br0), bh1 = f2tf(br1);
                uint32_t bl0 = __float_as_uint(br0 - __uint_as_float(bh0));
                uint32_t bl1 = __float_as_uint(br1 - __uint_as_float(bh1));
                mma8(acc[n], al, bh0, bh1);
                mma8(acc[n], ah, bl0, bl1);
                mma8(acc[n], ah, bh0, bh1);
            }
        }
    }
    int r0 = row0 + wp*16 + g;
    #pragma unroll
    for (int n = 0; n < 8; n++) {
        float* out = (n < 4) ? oa : ob;
        int col = (n & 3)*8 + 2*t4;
        *(float2*)&out[ r0     *D_ + col] = make_float2(acc[n][0], acc[n][1]);
        *(float2*)&out[(r0 + 8)*D_ + col] = make_float2(acc[n][2], acc[n][3]);
    }
}

// ---- V projection: grid (128 rowblk, 4 colblk, 4 idx) ----
__global__ __launch_bounds__(256, 4) void proj_v(VArgs args) {
    extern __shared__ float smf[];
    uint32_t sb;
    { uint64_t a = __cvta_generic_to_shared(smf); sb = (uint32_t)a; }
    int t = threadIdx.x;
    int wp = t >> 5, lane = t & 31;
    int g = lane >> 2, t4 = lane & 3;
    int row0 = blockIdx.x * 128;
    int col0 = blockIdx.y * 64;
    int idx = blockIdx.z;

    const float* wv = args.wv[idx];
    const float* X  = (idx == 0 || idx == 3) ? g_ecg : g_pcg;
    float* out = g_v[idx];

    #pragma unroll
    for (int i = 0; i < 4; i++) {
        int e = i*256 + t; int r = e >> 3, c4 = e & 7;
        cp16(sb + (r*PX + c4*4)*4, X + (row0 + r)*C_ + c4*4);
    }
    #pragma unroll
    for (int i = 0; i < 2; i++) {
        int e = i*256 + t; int k = e >> 4, c4 = e & 15;
        cp16(sb + (2*128*PX + k*PW + c4*4)*4, wv + k*C_ + col0 + c4*4);
    }
    CP_COMMIT();

    float acc[8][4];
    #pragma unroll
    for (int n = 0; n < 8; n++) { acc[n][0]=acc[n][1]=acc[n][2]=acc[n][3]=0.f; }

    for (int kc = 0; kc < 8; kc++) {
        CP_WAIT0();
        __syncthreads();
        int buf = kc & 1, nbuf = buf ^ 1;
        if (kc < 7) {
            #pragma unroll
            for (int i = 0; i < 4; i++) {
                int e = i*256 + t; int r = e >> 3, c4 = e & 7;
                cp16(sb + (nbuf*128*PX + r*PX + c4*4)*4,
                     X + (row0 + r)*C_ + (kc+1)*32 + c4*4);
            }
            #pragma unroll
            for (int i = 0; i < 2; i++) {
                int e = i*256 + t; int k = e >> 4, c4 = e & 15;
                cp16(sb + (2*128*PX + nbuf*32*PW + k*PW + c4*4)*4,
                     wv + ((kc+1)*32 + k)*C_ + col0 + c4*4);
            }
            CP_COMMIT();
        }
        const float* sX = smf + buf*128*PX;
        const float* sW = smf + 2*128*PX + buf*32*PW;
        #pragma unroll
        for (int kk = 0; kk < 4; kk++) {
            float ar[4];
            ar[0] = sX[(wp*16 + g    )*PX + kk*8 + t4];
            ar[1] = sX[(wp*16 + g + 8)*PX + kk*8 + t4];
            ar[2] = sX[(wp*16 + g    )*PX + kk*8 + t4 + 4];
            ar[3] = sX[(wp*16 + g + 8)*PX + kk*8 + t4 + 4];
            uint32_t ah[4], al[4];
            #pragma unroll
            for (int i = 0; i < 4; i++) {
                ah[i] = f2tf(ar[i]);
                al[i] = __float_as_uint(ar[i] - __uint_as_float(ah[i]));
            }
            #pragma unroll
            for (int n = 0; n < 8; n++) {
                float br0 = sW[(kk*8 + t4    )*PW + n*8 + g];
                float br1 = sW[(kk*8 + t4 + 4)*PW + n*8 + g];
                uint32_t bh0 = f2tf(br0), bh1 = f2tf(br1);
                uint32_t bl0 = __float_as_uint(br0 - __uint_as_float(bh0));
                uint32_t bl1 = __float_as_uint(br1 - __uint_as_float(bh1));
                mma8(acc[n], al, bh0, bh1);
                mma8(acc[n], ah, bl0, bl1);
                mma8(acc[n], ah, bh0, bh1);
            }
        }
    }
    int r0 = row0 + wp*16 + g;
    #pragma unroll
    for (int n = 0; n < 8; n++) {
        int col = col0 + n*8 + 2*t4;
        *(float2*)&out[ r0     *C_ + col] = make_float2(acc[n][0], acc[n][1]);
        *(float2*)&out[(r0 + 8)*C_ + col] = make_float2(acc[n][2], acc[n][3]);
    }
}

// ============ tf32 flash attention, raw staging + cp.async pipeline ============
// CTA: 64 query rows, 512 threads = 16 warps; 2 CTAs/SM.
// warp: rg = wp>>2 (16-row group), ch = wp&3 (8-key score group / 64-col quarter).
#define ROWS 64
#define KT   32
#define PQ   36
#define PK   36
#define PV   264
#define PP   36
#define AOFF_Q 0
#define AOFF_K (AOFF_Q + 64*PQ)            // 2304   (2 bufs x 32*36)
#define AOFF_V (AOFF_K + 2*32*PK)          // 4608   (2 bufs x 32*264)
#define AOFF_P (AOFF_V + 2*32*PV)          // 21504
#define AOFF_S (AOFF_P + 64*PP)            // 23808
#define ATTN_U32 (AOFF_S + 16*16)          // 24064
#define ATTN_SMEM (ATTN_U32*4)             // 96256 B

__global__ __launch_bounds__(512, 2) void attn_mma(float* __restrict__ dst,
        const float* __restrict__ alpha, const float* __restrict__ gamma) {
    extern __shared__ float smf[];
    uint32_t sb;
    { uint64_t a = __cvta_generic_to_shared(smf); sb = (uint32_t)a; }
    const float* sQ = smf + AOFF_Q;
    const float* sK = smf + AOFF_K;
    const uint32_t* sVu = (const uint32_t*)(smf + AOFF_V);
    uint32_t* sP = (uint32_t*)(smf + AOFF_P);
    float*    sS = smf + AOFF_S;

    int t = threadIdx.x;
    int wp = t >> 5, lane = t & 31;
    int g = lane >> 2, t4 = lane & 3;
    int rg = wp >> 2, ch = wp & 3;
    int b = blockIdx.y, h = blockIdx.z;
    int row0 = blockIdx.x * ROWS;
    int tokbase = b * L_;

    int idx_a = h ? 2 : 0;
    int idx_b = h ? 3 : 1;
    const float* coefp = h ? gamma : alpha;
    const float SC = 0.17677669529663687f;  // 1/sqrt(32)

    for (int pass = 0; pass < 2; pass++) {
        int idx = (pass == 0) ? idx_a : idx_b;
        const float* __restrict__ Q = g_q[idx];
        const float* __restrict__ K = g_k[idx];
        const float* __restrict__ V = g_v[idx];

        // ---- prologue: stage Q + tile 0 (K,V) via cp.async ----
        {
            int r = t >> 3, c4 = t & 7;   // 512 threads over 64x8 f4
            cp16(sb + (AOFF_Q + r*PQ + c4*4)*4,
                 Q + (tokbase + row0 + r)*D_ + c4*4);
            if (t < 256)
                cp16(sb + (AOFF_K + r*PK + c4*4)*4,
                     K + (tokbase + r)*D_ + c4*4);
            #pragma unroll
            for (int i = 0; i < 4; i++) {
                int e = i*512 + t; int rv = e >> 6, cv = e & 63;
                cp16(sb + (AOFF_V + rv*PV + cv*4)*4,
                     V + (tokbase + rv)*C_ + cv*4);
            }
            CP_COMMIT();
        }

        float acc[8][4];
        #pragma unroll
        for (int n = 0; n < 8; n++) { acc[n][0]=acc[n][1]=acc[n][2]=acc[n][3]=0.f; }
        float rs0 = 0.f, rs1 = 0.f;

        for (int kt = 0; kt < L_/KT; kt++) {
            CP_WAIT0();
            __syncthreads();
            int buf = kt & 1, nbuf = buf ^ 1;
            if (kt < L_/KT - 1) {
                int tok = tokbase + (kt+1)*KT;
                if (t < 256) {
                    int r = t >> 3, c4 = t & 7;
                    cp16(sb + (AOFF_K + nbuf*32*PK + r*PK + c4*4)*4,
                         K + (tok + r)*D_ + c4*4);
                }
                #pragma unroll
                for (int i = 0; i < 4; i++) {
                    int e = i*512 + t; int rv = e >> 6, cv = e & 63;
                    cp16(sb + (AOFF_V + nbuf*32*PV + rv*PV + cv*4)*4,
                         V + (tok + rv)*C_ + cv*4);
                }
                CP_COMMIT();
            }
            const float* sKb = sK + buf*32*PK;
            const uint32_t* sVb = sVu + buf*32*PV;

            // ---- scores (3xTF32): warp's 16 rows x 8 keys ----
            float s[4] = {0.f, 0.f, 0.f, 0.f};
            #pragma unroll
            for (int kk = 0; kk < 4; kk++) {
                float ar[4];
                ar[0] = sQ[(rg*16 + g    )*PQ + kk*8 + t4];
                ar[1] = sQ[(rg*16 + g + 8)*PQ + kk*8 + t4];
                ar[2] = sQ[(rg*16 + g    )*PQ + kk*8 + t4 + 4];
                ar[3] = sQ[(rg*16 + g + 8)*PQ + kk*8 + t4 + 4];
                uint32_t ah[4], al[4];
                #pragma unroll
                for (int i = 0; i < 4; i++) {
                    ah[i] = f2tf(ar[i]);
                    al[i] = __float_as_uint(ar[i] - __uint_as_float(ah[i]));
                }
                float br0 = sKb[(ch*8 + g)*PK + kk*8 + t4];
                float br1 = sKb[(ch*8 + g)*PK + kk*8 + t4 + 4];
                uint32_t bh0 = f2tf(br0), bh1 = f2tf(br1);
                uint32_t bl0 = __float_as_uint(br0 - __uint_as_float(bh0));
                uint32_t bl1 = __float_as_uint(br1 - __uint_as_float(bh1));
                mma8(s, al, bh0, bh1);
                mma8(s, ah, bl0, bl1);
                mma8(s, ah, bh0, bh1);
            }
            float p0 = __expf(s[0]*SC);
            float p1 = __expf(s[1]*SC);
            float p2 = __expf(s[2]*SC);
            float p3 = __expf(s[3]*SC);
            rs0 += p0 + p1;
            rs1 += p2 + p3;
            *(uint2*)&sP[(rg*16 + g    )*PP + ch*8 + 2*t4] = make_uint2(f2tf(p0), f2tf(p1));
            *(uint2*)&sP[(rg*16 + g + 8)*PP + ch*8 + 2*t4] = make_uint2(f2tf(p2), f2tf(p3));
            __syncthreads();

            // ---- P*V: warp's 16 rows x 64 cols (ch quarter), raw V ----
            #pragma unroll
            for (int kk = 0; kk < 4; kk++) {
                uint32_t a[4];
                a[0] = sP[(rg*16 + g    )*PP + kk*8 + t4];
                a[1] = sP[(rg*16 + g + 8)*PP + kk*8 + t4];
                a[2] = sP[(rg*16 + g    )*PP + kk*8 + t4 + 4];
                a[3] = sP[(rg*16 + g + 8)*PP + kk*8 + t4 + 4];
                #pragma unroll
                for (int n = 0; n < 8; n++) {
                    int col = ch*64 + n*8 + g;
                    uint32_t b0 = sVb[(kk*8 + t4    )*PV + col];
                    uint32_t b1 = sVb[(kk*8 + t4 + 4)*PV + col];
                    mma8(acc[n], a, b0, b1);
                }
            }
        }

        // ---- softmax denominators ----
        rs0 += __shfl_xor_sync(0xffffffffu, rs0, 1);
        rs0 += __shfl_xor_sync(0xffffffffu, rs0, 2);
        rs1 += __shfl_xor_sync(0xffffffffu, rs1, 1);
        rs1 += __shfl_xor_sync(0xffffffffu, rs1, 2);
        __syncthreads();   // sP/score area reuse barrier before sS writes
        if (t4 == 0) {
            sS[(rg*4 + ch)*16 + g    ] = rs0;
            sS[(rg*4 + ch)*16 + g + 8] = rs1;
        }
        __syncthreads();
        float den0 = 0.f, den1 = 0.f;
        #pragma unroll
        for (int c = 0; c < 4; c++) {
            den0 += sS[(rg*4 + c)*16 + g    ];
            den1 += sS[(rg*4 + c)*16 + g + 8];
        }
        float inv0 = 1.0f / den0;
        float inv1 = 1.0f / den1;

        int r0 = tokbase + row0 + rg*16 + g;
        if (pass == 0) {
            float* st = g_o[h];
            #pragma unroll
            for (int n = 0; n < 8; n++) {
                int col = ch*64 + n*8 + 2*t4;
                *(float2*)&st[ r0     *256 + col] = make_float2(acc[n][0]*inv0, acc[n][1]*inv0);
                *(float2*)&st[(r0 + 8)*256 + col] = make_float2(acc[n][2]*inv1, acc[n][3]*inv1);
            }
        } else {
            float cf = coefp[0];
            const float* st = g_o[h];
            int ooff = h * 256;
            #pragma unroll
            for (int n = 0; n < 8; n++) {
                int col = ch*64 + n*8 + 2*t4;
                float2 s0 = *(const float2*)&st[ r0     *256 + col];
                float2 s1 = *(const float2*)&st[(r0 + 8)*256 + col];
                float2 o0 = make_float2(acc[n][0]*inv0 + cf*s0.x,
                                        acc[n][1]*inv0 + cf*s0.y);
                float2 o1 = make_float2(acc[n][2]*inv1 + cf*s1.x,
                                        acc[n][3]*inv1 + cf*s1.y);
                *(float2*)&dst[ r0     *512 + ooff + col] = o0;
                *(float2*)&dst[(r0 + 8)*512 + ooff + col] = o1;
            }
        }
        __syncthreads();   // all warps done with sS/output before next pass restages
    }
}

extern "C" void kernel_launch(void* const* d_in, const int* in_sizes, int n_in,
                              void* d_out, int out_size) {
    const float* x = (const float*)d_in[0];
    const float* wt[12];
    for (int i = 0; i < 12; i++) wt[i] = (const float*)d_in[1+i];
    const float* alpha = (const float*)d_in[13];
    const float* gamma = (const float*)d_in[14];
    float* out = (float*)d_out;

    cudaFuncSetAttribute(proj_qk,
                         cudaFuncAttributeMaxDynamicSharedMemorySize, PROJ_SMEM);
    cudaFuncSetAttribute(proj_v,
                         cudaFuncAttributeMaxDynamicSharedMemorySize, PROJ_SMEM);
    cudaFuncSetAttribute(attn_mma,
                         cudaFuncAttributeMaxDynamicSharedMemorySize, ATTN_SMEM);

    split_kernel<<<2048, 256>>>((const float2*)x, NTOK*C_);

    // Q/K pairs grouped by shared source:
    //  y0: X=ecg  wa=w1->q0   wb=w2->k0
    //  y1: X=ecg  wa=w4->q1   wb=w11->k3
    //  y2: X=pcg  wa=w7->q2   wb=w5->k1
    //  y3: X=pcg  wa=w8->k2   wb=w10->q3
    QKArgs qk;
    qk.wa[0] = wt[0];  qk.wb[0] = wt[1];
    qk.wa[1] = wt[3];  qk.wb[1] = wt[10];
    qk.wa[2] = wt[6];  qk.wb[2] = wt[4];
    qk.wa[3] = wt[7];  qk.wb[3] = wt[9];
    proj_qk<<<dim3(NTOK/128, 4), 256, PROJ_SMEM>>>(qk);

    VArgs va;
    va.wv[0] = wt[2]; va.wv[1] = wt[5]; va.wv[2] = wt[8]; va.wv[3] = wt[11];
    proj_v<<<dim3(NTOK/128, 4, 4), 256, PROJ_SMEM>>>(va);

    dim3 ag(L_/ROWS, B_, 2);
    attn_mma<<<ag, 512, ATTN_SMEM>>>(out, alpha, gamma);
}

// round 5
// speedup vs baseline: 2.4737x; 1.0968x over previous
#include <cuda_runtime.h>
#include <stdint.h>

#define B_ 8
#define L_ 2048
#define C_ 256
#define D_ 32
#define NTOK (B_*L_)   // 16384

// -------- scratch (static device arrays: no allocation) --------
__device__ float g_ecg[NTOK*C_];
__device__ float g_pcg[NTOK*C_];
__device__ float g_q[4][NTOK*D_];
__device__ float g_k[4][NTOK*D_];
__device__ float g_v[4][NTOK*C_];
__device__ float g_o[2][NTOK*C_];   // intra-attention stash (per half)

// -------- helpers --------
__device__ __forceinline__ uint32_t f2tf(float x) {
    uint32_t u;
    asm("cvt.rna.tf32.f32 %0, %1;" : "=r"(u) : "f"(x));
    return u;
}
__device__ __forceinline__ void mma8(float* d, const uint32_t* a,
                                     uint32_t b0, uint32_t b1) {
    asm volatile(
        "mma.sync.aligned.m16n8k8.row.col.f32.tf32.tf32.f32 "
        "{%0,%1,%2,%3}, {%4,%5,%6,%7}, {%8,%9}, {%0,%1,%2,%3};"
        : "+f"(d[0]), "+f"(d[1]), "+f"(d[2]), "+f"(d[3])
        : "r"(a[0]), "r"(a[1]), "r"(a[2]), "r"(a[3]), "r"(b0), "r"(b1));
}
__device__ __forceinline__ void cp16(uint32_t dst, const void* src) {
    asm volatile("cp.async.cg.shared.global [%0], [%1], 16;" :: "r"(dst), "l"(src));
}
#define CP_COMMIT() asm volatile("cp.async.commit_group;")
#define CP_WAIT0()  asm volatile("cp.async.wait_group 0;")

// -------- split interleaved x[...,2] into two contiguous streams --------
__global__ void split_kernel(const float2* __restrict__ x2, int n) {
    int i = blockIdx.x*blockDim.x + threadIdx.x;
    int stride = gridDim.x*blockDim.x;
    for (; i < n; i += stride) {
        float2 v = x2[i];
        g_ecg[i] = v.x;
        g_pcg[i] = v.y;
    }
}

// ============ 3xTF32 projection GEMMs (raw staging + cp.async) ============
#define PX 36   // 4 mod 32
#define PW 72   // 8 mod 32
#define PROJ_SMEM ((2*128*PX + 2*32*PW)*4)   // 55296 B

struct QKArgs { const float* wa[4]; const float* wb[4]; };
struct VArgs  { const float* wv[4]; };

// ---- fused Q/K pair projection ----
__global__ __launch_bounds__(256, 4) void proj_qk(QKArgs args) {
    extern __shared__ float smf[];
    uint32_t sb;
    { uint64_t a = __cvta_generic_to_shared(smf); sb = (uint32_t)a; }
    int t = threadIdx.x;
    int wp = t >> 5, lane = t & 31;
    int g = lane >> 2, t4 = lane & 3;
    int row0 = blockIdx.x * 128;
    int y = blockIdx.y;

    const float* wa = args.wa[y];
    const float* wb = args.wb[y];
    const float* X  = (y < 2) ? g_ecg : g_pcg;
    float* oa = (y==0) ? g_q[0] : (y==1) ? g_q[1] : (y==2) ? g_q[2] : g_k[2];
    float* ob = (y==0) ? g_k[0] : (y==1) ? g_k[3] : (y==2) ? g_k[1] : g_q[3];

    #pragma unroll
    for (int i = 0; i < 4; i++) {
        int e = i*256 + t; int r = e >> 3, c4 = e & 7;
        cp16(sb + (r*PX + c4*4)*4, X + (row0 + r)*C_ + c4*4);
    }
    #pragma unroll
    for (int i = 0; i < 2; i++) {
        int e = i*256 + t; int k = e >> 4, c4 = e & 15;
        const float* src = (c4 < 8) ? (wa + k*D_ + c4*4) : (wb + k*D_ + (c4-8)*4);
        cp16(sb + (2*128*PX + k*PW + c4*4)*4, src);
    }
    CP_COMMIT();

    float acc[8][4];
    #pragma unroll
    for (int n = 0; n < 8; n++) { acc[n][0]=acc[n][1]=acc[n][2]=acc[n][3]=0.f; }

    for (int kc = 0; kc < 8; kc++) {
        CP_WAIT0();
        __syncthreads();
        int buf = kc & 1, nbuf = buf ^ 1;
        if (kc < 7) {
            #pragma unroll
            for (int i = 0; i < 4; i++) {
                int e = i*256 + t; int r = e >> 3, c4 = e & 7;
                cp16(sb + (nbuf*128*PX + r*PX + c4*4)*4,
                     X + (row0 + r)*C_ + (kc+1)*32 + c4*4);
            }
            #pragma unroll
            for (int i = 0; i < 2; i++) {
                int e = i*256 + t; int k = e >> 4, c4 = e & 15;
                int krow = (kc+1)*32 + k;
                const float* src = (c4 < 8) ? (wa + krow*D_ + c4*4)
                                            : (wb + krow*D_ + (c4-8)*4);
                cp16(sb + (2*128*PX + nbuf*32*PW + k*PW + c4*4)*4, src);
            }
            CP_COMMIT();
        }
        const float* sX = smf + buf*128*PX;
        const float* sW = smf + 2*128*PX + buf*32*PW;
        #pragma unroll
        for (int kk = 0; kk < 4; kk++) {
            float ar[4];
            ar[0] = sX[(wp*16 + g    )*PX + kk*8 + t4];
            ar[1] = sX[(wp*16 + g + 8)*PX + kk*8 + t4];
            ar[2] = sX[(wp*16 + g    )*PX + kk*8 + t4 + 4];
            ar[3] = sX[(wp*16 + g + 8)*PX + kk*8 + t4 + 4];
            uint32_t ah[4], al[4];
            #pragma unroll
            for (int i = 0; i < 4; i++) {
                ah[i] = f2tf(ar[i]);
                al[i] = __float_as_uint(ar[i] - __uint_as_float(ah[i]));
            }
            #pragma unroll
            for (int n = 0; n < 8; n++) {
                float br0 = sW[(kk*8 + t4    )*PW + n*8 + g];
                float br1 = sW[(kk*8 + t4 + 4)*PW + n*8 + g];
                uint32_t bh0 = f2tf(br0), bh1 = f2tf(br1);
                uint32_t bl0 = __float_as_uint(br0 - __uint_as_float(bh0));
                uint32_t bl1 = __float_as_uint(br1 - __uint_as_float(bh1));
                mma8(acc[n], al, bh0, bh1);
                mma8(acc[n], ah, bl0, bl1);
                mma8(acc[n], ah, bh0, bh1);
            }
        }
    }
    int r0 = row0 + wp*16 + g;
    #pragma unroll
    for (int n = 0; n < 8; n++) {
        float* out = (n < 4) ? oa : ob;
        int col = (n & 3)*8 + 2*t4;
        *(float2*)&out[ r0     *D_ + col] = make_float2(acc[n][0], acc[n][1]);
        *(float2*)&out[(r0 + 8)*D_ + col] = make_float2(acc[n][2], acc[n][3]);
    }
}

// ---- V projection ----
__global__ __launch_bounds__(256, 4) void proj_v(VArgs args) {
    extern __shared__ float smf[];
    uint32_t sb;
    { uint64_t a = __cvta_generic_to_shared(smf); sb = (uint32_t)a; }
    int t = threadIdx.x;
    int wp = t >> 5, lane = t & 31;
    int g = lane >> 2, t4 = lane & 3;
    int row0 = blockIdx.x * 128;
    int col0 = blockIdx.y * 64;
    int idx = blockIdx.z;

    const float* wv = args.wv[idx];
    const float* X  = (idx == 0 || idx == 3) ? g_ecg : g_pcg;
    float* out = g_v[idx];

    #pragma unroll
    for (int i = 0; i < 4; i++) {
        int e = i*256 + t; int r = e >> 3, c4 = e & 7;
        cp16(sb + (r*PX + c4*4)*4, X + (row0 + r)*C_ + c4*4);
    }
    #pragma unroll
    for (int i = 0; i < 2; i++) {
        int e = i*256 + t; int k = e >> 4, c4 = e & 15;
        cp16(sb + (2*128*PX + k*PW + c4*4)*4, wv + k*C_ + col0 + c4*4);
    }
    CP_COMMIT();

    float acc[8][4];
    #pragma unroll
    for (int n = 0; n < 8; n++) { acc[n][0]=acc[n][1]=acc[n][2]=acc[n][3]=0.f; }

    for (int kc = 0; kc < 8; kc++) {
        CP_WAIT0();
        __syncthreads();
        int buf = kc & 1, nbuf = buf ^ 1;
        if (kc < 7) {
            #pragma unroll
            for (int i = 0; i < 4; i++) {
                int e = i*256 + t; int r = e >> 3, c4 = e & 7;
                cp16(sb + (nbuf*128*PX + r*PX + c4*4)*4,
                     X + (row0 + r)*C_ + (kc+1)*32 + c4*4);
            }
            #pragma unroll
            for (int i = 0; i < 2; i++) {
                int e = i*256 + t; int k = e >> 4, c4 = e & 15;
                cp16(sb + (2*128*PX + nbuf*32*PW + k*PW + c4*4)*4,
                     wv + ((kc+1)*32 + k)*C_ + col0 + c4*4);
            }
            CP_COMMIT();
        }
        const float* sX = smf + buf*128*PX;
        const float* sW = smf + 2*128*PX + buf*32*PW;
        #pragma unroll
        for (int kk = 0; kk < 4; kk++) {
            float ar[4];
            ar[0] = sX[(wp*16 + g    )*PX + kk*8 + t4];
            ar[1] = sX[(wp*16 + g + 8)*PX + kk*8 + t4];
            ar[2] = sX[(wp*16 + g    )*PX + kk*8 + t4 + 4];
            ar[3] = sX[(wp*16 + g + 8)*PX + kk*8 + t4 + 4];
            uint32_t ah[4], al[4];
            #pragma unroll
            for (int i = 0; i < 4; i++) {
                ah[i] = f2tf(ar[i]);
                al[i] = __float_as_uint(ar[i] - __uint_as_float(ah[i]));
            }
            #pragma unroll
            for (int n = 0; n < 8; n++) {
                float br0 = sW[(kk*8 + t4    )*PW + n*8 + g];
                float br1 = sW[(kk*8 + t4 + 4)*PW + n*8 + g];
                uint32_t bh0 = f2tf(br0), bh1 = f2tf(br1);
                uint32_t bl0 = __float_as_uint(br0 - __uint_as_float(bh0));
                uint32_t bl1 = __float_as_uint(br1 - __uint_as_float(bh1));
                mma8(acc[n], al, bh0, bh1);
                mma8(acc[n], ah, bl0, bl1);
                mma8(acc[n], ah, bh0, bh1);
            }
        }
    }
    int r0 = row0 + wp*16 + g;
    #pragma unroll
    for (int n = 0; n < 8; n++) {
        int col = col0 + n*8 + 2*t4;
        *(float2*)&out[ r0     *C_ + col] = make_float2(acc[n][0], acc[n][1]);
        *(float2*)&out[(r0 + 8)*C_ + col] = make_float2(acc[n][2], acc[n][3]);
    }
}

// ============ tf32 flash attention: 256 thr, 8 warps, warp = 32 rows x 64 cols ============
// rg = wp>>2 in {0,1}: rows rg*32 + mt*16 + {g, g+8} for m-tiles mt in {0,1}
// ch = wp&3:           score keys ch*8..+8, output cols ch*64..+64
#define ROWS 64
#define KT   32
#define PQ   36
#define PK   36
#define PVA  264
#define PP   36
#define AOFF_Q 0
#define AOFF_K (AOFF_Q + 64*PQ)            // 2304  (2 bufs x 32*36)
#define AOFF_V (AOFF_K + 2*32*PK)          //       (2 bufs x 32*264)
#define AOFF_P (AOFF_V + 2*32*PVA)
#define AOFF_S (AOFF_P + 64*PP)
#define ATTN_U32 (AOFF_S + 4*64)           // 24064
#define ATTN_SMEM (ATTN_U32*4)             // 96256 B

__global__ __launch_bounds__(256, 2) void attn_mma(float* __restrict__ dst,
        const float* __restrict__ alpha, const float* __restrict__ gamma) {
    extern __shared__ float smf[];
    uint32_t sb;
    { uint64_t a = __cvta_generic_to_shared(smf); sb = (uint32_t)a; }
    const float* sQ = smf + AOFF_Q;
    const float* sK = smf + AOFF_K;
    const uint32_t* sVu = (const uint32_t*)(smf + AOFF_V);
    uint32_t* sP = (uint32_t*)(smf + AOFF_P);
    float*    sS = smf + AOFF_S;

    int t = threadIdx.x;
    int wp = t >> 5, lane = t & 31;
    int g = lane >> 2, t4 = lane & 3;
    int rg = wp >> 2, ch = wp & 3;
    int b = blockIdx.y, h = blockIdx.z;
    int row0 = blockIdx.x * ROWS;
    int tokbase = b * L_;

    int idx_a = h ? 2 : 0;
    int idx_b = h ? 3 : 1;
    const float* coefp = h ? gamma : alpha;
    const float SC = 0.17677669529663687f;  // 1/sqrt(32)

    for (int pass = 0; pass < 2; pass++) {
        int idx = (pass == 0) ? idx_a : idx_b;
        const float* __restrict__ Q = g_q[idx];
        const float* __restrict__ K = g_k[idx];
        const float* __restrict__ V = g_v[idx];

        // ---- prologue: stage Q + tile 0 (K,V) ----
        __syncthreads();   // prior-pass smem consumers done before restage
        {
            #pragma unroll
            for (int i = 0; i < 2; i++) {
                int e = i*256 + t; int r = e >> 3, c4 = e & 7;
                cp16(sb + (AOFF_Q + r*PQ + c4*4)*4,
                     Q + (tokbase + row0 + r)*D_ + c4*4);
            }
            { int r = t >> 3, c4 = t & 7;
              cp16(sb + (AOFF_K + r*PK + c4*4)*4,
                   K + (tokbase + r)*D_ + c4*4); }
            #pragma unroll
            for (int i = 0; i < 8; i++) {
                int e = i*256 + t; int rv = e >> 6, cv = e & 63;
                cp16(sb + (AOFF_V + rv*PVA + cv*4)*4,
                     V + (tokbase + rv)*C_ + cv*4);
            }
            CP_COMMIT();
        }
        CP_WAIT0();
        __syncthreads();

        // ---- hoist raw Q fragments for this warp's 32 rows (whole pass) ----
        float qraw[2][4][4];
        #pragma unroll
        for (int mt = 0; mt < 2; mt++) {
            int rb = rg*32 + mt*16;
            #pragma unroll
            for (int kk = 0; kk < 4; kk++) {
                qraw[mt][kk][0] = sQ[(rb + g    )*PQ + kk*8 + t4];
                qraw[mt][kk][1] = sQ[(rb + g + 8)*PQ + kk*8 + t4];
                qraw[mt][kk][2] = sQ[(rb + g    )*PQ + kk*8 + t4 + 4];
                qraw[mt][kk][3] = sQ[(rb + g + 8)*PQ + kk*8 + t4 + 4];
            }
        }

        float acc[2][8][4];
        #pragma unroll
        for (int mt = 0; mt < 2; mt++)
            #pragma unroll
            for (int n = 0; n < 8; n++)
                acc[mt][n][0]=acc[mt][n][1]=acc[mt][n][2]=acc[mt][n][3]=0.f;
        float lsum[2][2] = {{0.f,0.f},{0.f,0.f}};

        for (int kt = 0; kt < L_/KT; kt++) {
            int buf = kt & 1, nbuf = buf ^ 1;
            if (kt < L_/KT - 1) {
                int tok = tokbase + (kt+1)*KT;
                { int r = t >> 3, c4 = t & 7;
                  cp16(sb + (AOFF_K + nbuf*32*PK + r*PK + c4*4)*4,
                       K + (tok + r)*D_ + c4*4); }
                #pragma unroll
                for (int i = 0; i < 8; i++) {
                    int e = i*256 + t; int rv = e >> 6, cv = e & 63;
                    cp16(sb + (AOFF_V + nbuf*32*PVA + rv*PVA + cv*4)*4,
                         V + (tok + rv)*C_ + cv*4);
                }
                CP_COMMIT();
            }
            const float* sKb = sK + buf*32*PK;
            const uint32_t* sVb = sVu + buf*32*PVA;

            // ---- scores (3xTF32): 2 m-tiles x 8 keys ----
            float s[2][4];
            s[0][0]=s[0][1]=s[0][2]=s[0][3]=0.f;
            s[1][0]=s[1][1]=s[1][2]=s[1][3]=0.f;
            #pragma unroll
            for (int kk = 0; kk < 4; kk++) {
                float br0 = sKb[(ch*8 + g)*PK + kk*8 + t4];
                float br1 = sKb[(ch*8 + g)*PK + kk*8 + t4 + 4];
                uint32_t bh0 = f2tf(br0), bh1 = f2tf(br1);
                uint32_t bl0 = __float_as_uint(br0 - __uint_as_float(bh0));
                uint32_t bl1 = __float_as_uint(br1 - __uint_as_float(bh1));
                #pragma unroll
                for (int mt = 0; mt < 2; mt++) {
                    uint32_t ah[4], al[4];
                    #pragma unroll
                    for (int i = 0; i < 4; i++) {
                        float ar = qraw[mt][kk][i];
                        ah[i] = f2tf(ar);
                        al[i] = __float_as_uint(ar - __uint_as_float(ah[i]));
                    }
                    mma8(s[mt], al, bh0, bh1);
                    mma8(s[mt], ah, bl0, bl1);
                    mma8(s[mt], ah, bh0, bh1);
                }
            }
            #pragma unroll
            for (int mt = 0; mt < 2; mt++) {
                int rb = rg*32 + mt*16;
                float p0 = __expf(s[mt][0]*SC);
                float p1 = __expf(s[mt][1]*SC);
                float p2 = __expf(s[mt][2]*SC);
                float p3 = __expf(s[mt][3]*SC);
                lsum[mt][0] += p0 + p1;
                lsum[mt][1] += p2 + p3;
                *(uint2*)&sP[(rb + g    )*PP + ch*8 + 2*t4] = make_uint2(f2tf(p0), f2tf(p1));
                *(uint2*)&sP[(rb + g + 8)*PP + ch*8 + 2*t4] = make_uint2(f2tf(p2), f2tf(p3));
            }
            __syncthreads();

            // ---- P*V: 2 m-tiles x 64 cols, V frags shared across m-tiles ----
            #pragma unroll
            for (int kk = 0; kk < 4; kk++) {
                uint32_t a[2][4];
                #pragma unroll
                for (int mt = 0; mt < 2; mt++) {
                    int rb = rg*32 + mt*16;
                    a[mt][0] = sP[(rb + g    )*PP + kk*8 + t4];
                    a[mt][1] = sP[(rb + g + 8)*PP + kk*8 + t4];
                    a[mt][2] = sP[(rb + g    )*PP + kk*8 + t4 + 4];
                    a[mt][3] = sP[(rb + g + 8)*PP + kk*8 + t4 + 4];
                }
                #pragma unroll
                for (int n = 0; n < 8; n++) {
                    int col = ch*64 + n*8 + g;
                    uint32_t b0 = sVb[(kk*8 + t4    )*PVA + col];
                    uint32_t b1 = sVb[(kk*8 + t4 + 4)*PVA + col];
                    mma8(acc[0][n], a[0], b0, b1);
                    mma8(acc[1][n], a[1], b0, b1);
                }
            }
            if (kt < L_/KT - 1) {
                CP_WAIT0();
            }
            __syncthreads();   // next K/V ready AND sP consumed before rewrite
        }

        // ---- softmax denominators (reduce over t4, then over ch via sS) ----
        #pragma unroll
        for (int mt = 0; mt < 2; mt++) {
            #pragma unroll
            for (int j = 0; j < 2; j++) {
                float v = lsum[mt][j];
                v += __shfl_xor_sync(0xffffffffu, v, 1);
                v += __shfl_xor_sync(0xffffffffu, v, 2);
                lsum[mt][j] = v;
            }
        }
        if (t4 == 0) {
            #pragma unroll
            for (int mt = 0; mt < 2; mt++) {
                int rb = rg*32 + mt*16;
                sS[ch*64 + rb + g    ] = lsum[mt][0];
                sS[ch*64 + rb + g + 8] = lsum[mt][1];
            }
        }
        __syncthreads();
        float inv[2][2];
        #pragma unroll
        for (int mt = 0; mt < 2; mt++) {
            int rb = rg*32 + mt*16;
            float d0 = 0.f, d1 = 0.f;
            #pragma unroll
            for (int c = 0; c < 4; c++) {
                d0 += sS[c*64 + rb + g    ];
                d1 += sS[c*64 + rb + g + 8];
            }
            inv[mt][0] = 1.0f / d0;
            inv[mt][1] = 1.0f / d1;
        }

        if (pass == 0) {
            float* st = g_o[h];
            #pragma unroll
            for (int mt = 0; mt < 2; mt++) {
                int r0 = tokbase + row0 + rg*32 + mt*16 + g;
                #pragma unroll
                for (int n = 0; n < 8; n++) {
                    int col = ch*64 + n*8 + 2*t4;
                    *(float2*)&st[ r0     *256 + col] =
                        make_float2(acc[mt][n][0]*inv[mt][0], acc[mt][n][1]*inv[mt][0]);
                    *(float2*)&st[(r0 + 8)*256 + col] =
                        make_float2(acc[mt][n][2]*inv[mt][1], acc[mt][n][3]*inv[mt][1]);
                }
            }
        } else {
            float cf = coefp[0];
            const float* st = g_o[h];
            int ooff = h * 256;
            #pragma unroll
            for (int mt = 0; mt < 2; mt++) {
                int r0 = tokbase + row0 + rg*32 + mt*16 + g;
                #pragma unroll
                for (int n = 0; n < 8; n++) {
                    int col = ch*64 + n*8 + 2*t4;
                    float2 s0 = *(const float2*)&st[ r0     *256 + col];
                    float2 s1 = *(const float2*)&st[(r0 + 8)*256 + col];
                    float2 o0 = make_float2(acc[mt][n][0]*inv[mt][0] + cf*s0.x,
                                            acc[mt][n][1]*inv[mt][0] + cf*s0.y);
                    float2 o1 = make_float2(acc[mt][n][2]*inv[mt][1] + cf*s1.x,
                                            acc[mt][n][3]*inv[mt][1] + cf*s1.y);
                    *(float2*)&dst[ r0     *512 + ooff + col] = o0;
                    *(float2*)&dst[(r0 + 8)*512 + ooff + col] = o1;
                }
            }
        }
    }
}

extern "C" void kernel_launch(void* const* d_in, const int* in_sizes, int n_in,
                              void* d_out, int out_size) {
    const float* x = (const float*)d_in[0];
    const float* wt[12];
    for (int i = 0; i < 12; i++) wt[i] = (const float*)d_in[1+i];
    const float* alpha = (const float*)d_in[13];
    const float* gamma = (const float*)d_in[14];
    float* out = (float*)d_out;

    cudaFuncSetAttribute(proj_qk,
                         cudaFuncAttributeMaxDynamicSharedMemorySize, PROJ_SMEM);
    cudaFuncSetAttribute(proj_v,
                         cudaFuncAttributeMaxDynamicSharedMemorySize, PROJ_SMEM);
    cudaFuncSetAttribute(attn_mma,
                         cudaFuncAttributeMaxDynamicSharedMemorySize, ATTN_SMEM);

    split_kernel<<<2048, 256>>>((const float2*)x, NTOK*C_);

    QKArgs qk;
    qk.wa[0] = wt[0];  qk.wb[0] = wt[1];
    qk.wa[1] = wt[3];  qk.wb[1] = wt[10];
    qk.wa[2] = wt[6];  qk.wb[2] = wt[4];
    qk.wa[3] = wt[7];  qk.wb[3] = wt[9];
    proj_qk<<<dim3(NTOK/128, 4), 256, PROJ_SMEM>>>(qk);

    VArgs va;
    va.wv[0] = wt[2]; va.wv[1] = wt[5]; va.wv[2] = wt[8]; va.wv[3] = wt[11];
    proj_v<<<dim3(NTOK/128, 4, 4), 256, PROJ_SMEM>>>(va);

    dim3 ag(L_/ROWS, B_, 2);
    attn_mma<<<ag, 256, ATTN_SMEM>>>(out, alpha, gamma);
}

// round 6
// speedup vs baseline: 2.9439x; 1.1901x over previous
#include <cuda_runtime.h>
#include <stdint.h>

#define B_ 8
#define L_ 2048
#define C_ 256
#define D_ 32
#define NTOK (B_*L_)   // 16384

// -------- scratch (static device arrays: no allocation) --------
__device__ float g_ecg[NTOK*C_];
__device__ float g_pcg[NTOK*C_];
__device__ float g_q[4][NTOK*D_];
__device__ uint32_t g_khb[4][NTOK*(D_/2)];   // K hi, packed bf16x2 along dim
__device__ uint32_t g_klb[4][NTOK*(D_/2)];   // K lo residual
__device__ float g_v[4][NTOK*C_];
__device__ float g_o[2][NTOK*C_];   // intra-attention stash (per half)

// -------- helpers --------
__device__ __forceinline__ uint32_t f2tf(float x) {
    uint32_t u;
    asm("cvt.rna.tf32.f32 %0, %1;" : "=r"(u) : "f"(x));
    return u;
}
__device__ __forceinline__ uint32_t packbf(float lo, float hi) {
    uint32_t r;
    asm("cvt.rn.bf16x2.f32 %0, %1, %2;" : "=r"(r) : "f"(hi), "f"(lo));
    return r;
}
__device__ __forceinline__ float bflo(uint32_t u) { return __uint_as_float(u << 16); }
__device__ __forceinline__ float bfhi(uint32_t u) { return __uint_as_float(u & 0xFFFF0000u); }

__device__ __forceinline__ void mma8(float* d, const uint32_t* a,
                                     uint32_t b0, uint32_t b1) {
    asm volatile(
        "mma.sync.aligned.m16n8k8.row.col.f32.tf32.tf32.f32 "
        "{%0,%1,%2,%3}, {%4,%5,%6,%7}, {%8,%9}, {%0,%1,%2,%3};"
        : "+f"(d[0]), "+f"(d[1]), "+f"(d[2]), "+f"(d[3])
        : "r"(a[0]), "r"(a[1]), "r"(a[2]), "r"(a[3]), "r"(b0), "r"(b1));
}
__device__ __forceinline__ void mma16(float* d, const uint32_t* a,
                                      uint32_t b0, uint32_t b1) {
    asm volatile(
        "mma.sync.aligned.m16n8k16.row.col.f32.bf16.bf16.f32 "
        "{%0,%1,%2,%3}, {%4,%5,%6,%7}, {%8,%9}, {%0,%1,%2,%3};"
        : "+f"(d[0]), "+f"(d[1]), "+f"(d[2]), "+f"(d[3])
        : "r"(a[0]), "r"(a[1]), "r"(a[2]), "r"(a[3]), "r"(b0), "r"(b1));
}
__device__ __forceinline__ void cp16(uint32_t dst, const void* src) {
    asm volatile("cp.async.cg.shared.global [%0], [%1], 16;" :: "r"(dst), "l"(src));
}
#define CP_COMMIT() asm volatile("cp.async.commit_group;")
#define CP_WAIT0()  asm volatile("cp.async.wait_group 0;")

// -------- split interleaved x[...,2] into two contiguous streams --------
__global__ void split_kernel(const float2* __restrict__ x2, int n) {
    int i = blockIdx.x*blockDim.x + threadIdx.x;
    int stride = gridDim.x*blockDim.x;
    for (; i < n; i += stride) {
        float2 v = x2[i];
        g_ecg[i] = v.x;
        g_pcg[i] = v.y;
    }
}

// ============ 3xTF32 projection GEMMs (raw staging + cp.async) ============
#define PX 36   // 4 mod 32
#define PW 72   // 8 mod 32
#define PROJ_SMEM ((2*128*PX + 2*32*PW)*4)   // 55296 B

struct QKArgs { const float* wa[4]; const float* wb[4]; };
struct VArgs  { const float* wv[4]; };

// ---- fused Q/K pair projection: Q -> f32, K -> pre-split bf16x2 planes ----
__global__ __launch_bounds__(256, 4) void proj_qk(QKArgs args) {
    extern __shared__ float smf[];
    uint32_t sb;
    { uint64_t a = __cvta_generic_to_shared(smf); sb = (uint32_t)a; }
    int t = threadIdx.x;
    int wp = t >> 5, lane = t & 31;
    int g = lane >> 2, t4 = lane & 3;
    int row0 = blockIdx.x * 128;
    int y = blockIdx.y;

    const float* wa = args.wa[y];
    const float* wb = args.wb[y];
    const float* X  = (y < 2) ? g_ecg : g_pcg;
    // q outputs: y0->q0, y1->q1, y2->q2, y3->q3 (q is oa for y<3, ob for y3)
    float* qout = (y==0) ? g_q[0] : (y==1) ? g_q[1] : (y==2) ? g_q[2] : g_q[3];
    // k outputs: y0->k0, y1->k3, y2->k1, y3->k2
    int kidx = (y==0) ? 0 : (y==1) ? 3 : (y==2) ? 1 : 2;
    uint32_t* khb = g_khb[kidx];
    uint32_t* klb = g_klb[kidx];
    bool k_is_a = (y == 3);   // for y3, the "wa" slot holds the K weight

    #pragma unroll
    for (int i = 0; i < 4; i++) {
        int e = i*256 + t; int r = e >> 3, c4 = e & 7;
        cp16(sb + (r*PX + c4*4)*4, X + (row0 + r)*C_ + c4*4);
    }
    #pragma unroll
    for (int i = 0; i < 2; i++) {
        int e = i*256 + t; int k = e >> 4, c4 = e & 15;
        const float* src = (c4 < 8) ? (wa + k*D_ + c4*4) : (wb + k*D_ + (c4-8)*4);
        cp16(sb + (2*128*PX + k*PW + c4*4)*4, src);
    }
    CP_COMMIT();

    float acc[8][4];
    #pragma unroll
    for (int n = 0; n < 8; n++) { acc[n][0]=acc[n][1]=acc[n][2]=acc[n][3]=0.f; }

    for (int kc = 0; kc < 8; kc++) {
        CP_WAIT0();
        __syncthreads();
        int buf = kc & 1, nbuf = buf ^ 1;
        if (kc < 7) {
            #pragma unroll
            for (int i = 0; i < 4; i++) {
                int e = i*256 + t; int r = e >> 3, c4 = e & 7;
                cp16(sb + (nbuf*128*PX + r*PX + c4*4)*4,
                     X + (row0 + r)*C_ + (kc+1)*32 + c4*4);
            }
            #pragma unroll
            for (int i = 0; i < 2; i++) {
                int e = i*256 + t; int k = e >> 4, c4 = e & 15;
                int krow = (kc+1)*32 + k;
                const float* src = (c4 < 8) ? (wa + krow*D_ + c4*4)
                                            : (wb + krow*D_ + (c4-8)*4);
                cp16(sb + (2*128*PX + nbuf*32*PW + k*PW + c4*4)*4, src);
            }
            CP_COMMIT();
        }
        const float* sX = smf + buf*128*PX;
        const float* sW = smf + 2*128*PX + buf*32*PW;
        #pragma unroll
        for (int kk = 0; kk < 4; kk++) {
            float ar[4];
            ar[0] = sX[(wp*16 + g    )*PX + kk*8 + t4];
            ar[1] = sX[(wp*16 + g + 8)*PX + kk*8 + t4];
            ar[2] = sX[(wp*16 + g    )*PX + kk*8 + t4 + 4];
            ar[3] = sX[(wp*16 + g + 8)*PX + kk*8 + t4 + 4];
            uint32_t ah[4], al[4];
            #pragma unroll
            for (int i = 0; i < 4; i++) {
                ah[i] = f2tf(ar[i]);
                al[i] = __float_as_uint(ar[i] - __uint_as_float(ah[i]));
            }
            #pragma unroll
            for (int n = 0; n < 8; n++) {
                float br0 = sW[(kk*8 + t4    )*PW + n*8 + g];
                float br1 = sW[(kk*8 + t4 + 4)*PW + n*8 + g];
                uint32_t bh0 = f2tf(br0), bh1 = f2tf(br1);
                uint32_t bl0 = __float_as_uint(br0 - __uint_as_float(bh0));
                uint32_t bl1 = __float_as_uint(br1 - __uint_as_float(bh1));
                mma8(acc[n], al, bh0, bh1);
                mma8(acc[n], ah, bl0, bl1);
                mma8(acc[n], ah, bh0, bh1);
            }
        }
    }
    int r0 = row0 + wp*16 + g;
    #pragma unroll
    for (int n = 0; n < 8; n++) {
        bool is_k = k_is_a ? (n < 4) : (n >= 4);
        if (!is_k) {
            int col = (n & 3)*8 + 2*t4;
            *(float2*)&qout[ r0     *D_ + col] = make_float2(acc[n][0], acc[n][1]);
            *(float2*)&qout[(r0 + 8)*D_ + col] = make_float2(acc[n][2], acc[n][3]);
        } else {
            int ci = (n & 3)*4 + t4;    // packed pair index along dim
            uint32_t h0 = packbf(acc[n][0], acc[n][1]);
            uint32_t l0 = packbf(acc[n][0] - bflo(h0), acc[n][1] - bfhi(h0));
            uint32_t h1 = packbf(acc[n][2], acc[n][3]);
            uint32_t l1 = packbf(acc[n][2] - bflo(h1), acc[n][3] - bfhi(h1));
            khb[ r0     *16 + ci] = h0;  klb[ r0     *16 + ci] = l0;
            khb[(r0 + 8)*16 + ci] = h1;  klb[(r0 + 8)*16 + ci] = l1;
        }
    }
}

// ---- V projection ----
__global__ __launch_bounds__(256, 4) void proj_v(VArgs args) {
    extern __shared__ float smf[];
    uint32_t sb;
    { uint64_t a = __cvta_generic_to_shared(smf); sb = (uint32_t)a; }
    int t = threadIdx.x;
    int wp = t >> 5, lane = t & 31;
    int g = lane >> 2, t4 = lane & 3;
    int row0 = blockIdx.x * 128;
    int col0 = blockIdx.y * 64;
    int idx = blockIdx.z;

    const float* wv = args.wv[idx];
    const float* X  = (idx == 0 || idx == 3) ? g_ecg : g_pcg;
    float* out = g_v[idx];

    #pragma unroll
    for (int i = 0; i < 4; i++) {
        int e = i*256 + t; int r = e >> 3, c4 = e & 7;
        cp16(sb + (r*PX + c4*4)*4, X + (row0 + r)*C_ + c4*4);
    }
    #pragma unroll
    for (int i = 0; i < 2; i++) {
        int e = i*256 + t; int k = e >> 4, c4 = e & 15;
        cp16(sb + (2*128*PX + k*PW + c4*4)*4, wv + k*C_ + col0 + c4*4);
    }
    CP_COMMIT();

    float acc[8][4];
    #pragma unroll
    for (int n = 0; n < 8; n++) { acc[n][0]=acc[n][1]=acc[n][2]=acc[n][3]=0.f; }

    for (int kc = 0; kc < 8; kc++) {
        CP_WAIT0();
        __syncthreads();
        int buf = kc & 1, nbuf = buf ^ 1;
        if (kc < 7) {
            #pragma unroll
            for (int i = 0; i < 4; i++) {
                int e = i*256 + t; int r = e >> 3, c4 = e & 7;
                cp16(sb + (nbuf*128*PX + r*PX + c4*4)*4,
                     X + (row0 + r)*C_ + (kc+1)*32 + c4*4);
            }
            #pragma unroll
            for (int i = 0; i < 2; i++) {
                int e = i*256 + t; int k = e >> 4, c4 = e & 15;
                cp16(sb + (2*128*PX + nbuf*32*PW + k*PW + c4*4)*4,
                     wv + ((kc+1)*32 + k)*C_ + col0 + c4*4);
            }
            CP_COMMIT();
        }
        const float* sX = smf + buf*128*PX;
        const float* sW = smf + 2*128*PX + buf*32*PW;
        #pragma unroll
        for (int kk = 0; kk < 4; kk++) {
            float ar[4];
            ar[0] = sX[(wp*16 + g    )*PX + kk*8 + t4];
            ar[1] = sX[(wp*16 + g + 8)*PX + kk*8 + t4];
            ar[2] = sX[(wp*16 + g    )*PX + kk*8 + t4 + 4];
            ar[3] = sX[(wp*16 + g + 8)*PX + kk*8 + t4 + 4];
            uint32_t ah[4], al[4];
            #pragma unroll
            for (int i = 0; i < 4; i++) {
                ah[i] = f2tf(ar[i]);
                al[i] = __float_as_uint(ar[i] - __uint_as_float(ah[i]));
            }
            #pragma unroll
            for (int n = 0; n < 8; n++) {
                float br0 = sW[(kk*8 + t4    )*PW + n*8 + g];
                float br1 = sW[(kk*8 + t4 + 4)*PW + n*8 + g];
                uint32_t bh0 = f2tf(br0), bh1 = f2tf(br1);
                uint32_t bl0 = __float_as_uint(br0 - __uint_as_float(bh0));
                uint32_t bl1 = __float_as_uint(br1 - __uint_as_float(bh1));
                mma8(acc[n], al, bh0, bh1);
                mma8(acc[n], ah, bl0, bl1);
                mma8(acc[n], ah, bh0, bh1);
            }
        }
    }
    int r0 = row0 + wp*16 + g;
    #pragma unroll
    for (int n = 0; n < 8; n++) {
        int col = col0 + n*8 + 2*t4;
        *(float2*)&out[ r0     *C_ + col] = make_float2(acc[n][0], acc[n][1]);
        *(float2*)&out[(r0 + 8)*C_ + col] = make_float2(acc[n][2], acc[n][3]);
    }
}

// ============ attention: bf16x3 scores + tf32 P*V ============
// 256 thr, 8 warps; warp = 32 rows (rg) x 64 cols / 8 keys (ch)
#define ROWS 64
#define KT   32
#define PQ   36
#define PKP  20     // packed K plane row stride (u32); conflict-free for 20g+t4
#define PVA  264
#define PP   36
#define AOFF_Q  0
#define AOFF_KH (AOFF_Q  + 64*PQ)           // 2304
#define AOFF_KL (AOFF_KH + 2*32*PKP)        // 3584
#define AOFF_V  (AOFF_KL + 2*32*PKP)        // 4864
#define AOFF_P  (AOFF_V  + 2*32*PVA)        // 21760
#define AOFF_S  (AOFF_P  + 64*PP)           // 24064
#define ATTN_U32 (AOFF_S + 256)             // 24320
#define ATTN_SMEM (ATTN_U32*4)              // 97280 B

__global__ __launch_bounds__(256, 2) void attn_mma(float* __restrict__ dst,
        const float* __restrict__ alpha, const float* __restrict__ gamma) {
    extern __shared__ float smf[];
    uint32_t sb;
    { uint64_t a = __cvta_generic_to_shared(smf); sb = (uint32_t)a; }
    const float*    sQ  = smf + AOFF_Q;
    const uint32_t* sKh = (const uint32_t*)(smf + AOFF_KH);
    const uint32_t* sKl = (const uint32_t*)(smf + AOFF_KL);
    const uint32_t* sVu = (const uint32_t*)(smf + AOFF_V);
    uint32_t* sPu = (uint32_t*)(smf + AOFF_P);
    float*    sPf = smf + AOFF_P;
    float*    sS  = smf + AOFF_S;

    int t = threadIdx.x;
    int wp = t >> 5, lane = t & 31;
    int g = lane >> 2, t4 = lane & 3;
    int rg = wp >> 2, ch = wp & 3;
    int b = blockIdx.y, h = blockIdx.z;
    int row0 = blockIdx.x * ROWS;
    int tokbase = b * L_;

    int idx_a = h ? 2 : 0;
    int idx_b = h ? 3 : 1;
    const float* coefp = h ? gamma : alpha;
    const float SC = 0.17677669529663687f;  // 1/sqrt(32)

    for (int pass = 0; pass < 2; pass++) {
        int idx = (pass == 0) ? idx_a : idx_b;
        const float*    __restrict__ Q  = g_q[idx];
        const uint32_t* __restrict__ KH = g_khb[idx];
        const uint32_t* __restrict__ KL = g_klb[idx];
        const float*    __restrict__ V  = g_v[idx];

        // ---- prologue: stage Q + tile 0 (K planes, V) ----
        __syncthreads();   // prior-pass smem consumers done before restage
        {
            #pragma unroll
            for (int i = 0; i < 2; i++) {
                int e = i*256 + t; int r = e >> 3, c4 = e & 7;
                cp16(sb + (AOFF_Q + r*PQ + c4*4)*4,
                     Q + (tokbase + row0 + r)*D_ + c4*4);
            }
            {
                int key = (t & 127) >> 2, c4 = t & 3;
                if (t < 128)
                    cp16(sb + (AOFF_KH + key*PKP + c4*4)*4,
                         KH + (tokbase + key)*16 + c4*4);
                else
                    cp16(sb + (AOFF_KL + key*PKP + c4*4)*4,
                         KL + (tokbase + key)*16 + c4*4);
            }
            #pragma unroll
            for (int i = 0; i < 8; i++) {
                int e = i*256 + t; int rv = e >> 6, cv = e & 63;
                cp16(sb + (AOFF_V + rv*PVA + cv*4)*4,
                     V + (tokbase + rv)*C_ + cv*4);
            }
            CP_COMMIT();
        }
        CP_WAIT0();
        __syncthreads();

        // ---- hoist Q as packed bf16 hi/lo A-fragments (whole pass) ----
        uint32_t qh[2][2][4], ql[2][2][4];
        #pragma unroll
        for (int mt = 0; mt < 2; mt++) {
            int rb = rg*32 + mt*16;
            #pragma unroll
            for (int kb = 0; kb < 2; kb++) {
                float2 x0 = *(const float2*)&sQ[(rb + g    )*PQ + kb*16 + 2*t4];
                float2 x1 = *(const float2*)&sQ[(rb + g + 8)*PQ + kb*16 + 2*t4];
                float2 x2 = *(const float2*)&sQ[(rb + g    )*PQ + kb*16 + 2*t4 + 8];
                float2 x3 = *(const float2*)&sQ[(rb + g + 8)*PQ + kb*16 + 2*t4 + 8];
                uint32_t h0 = packbf(x0.x, x0.y), h1 = packbf(x1.x, x1.y);
                uint32_t h2 = packbf(x2.x, x2.y), h3 = packbf(x3.x, x3.y);
                qh[mt][kb][0] = h0; qh[mt][kb][1] = h1;
                qh[mt][kb][2] = h2; qh[mt][kb][3] = h3;
                ql[mt][kb][0] = packbf(x0.x - bflo(h0), x0.y - bfhi(h0));
                ql[mt][kb][1] = packbf(x1.x - bflo(h1), x1.y - bfhi(h1));
                ql[mt][kb][2] = packbf(x2.x - bflo(h2), x2.y - bfhi(h2));
                ql[mt][kb][3] = packbf(x3.x - bflo(h3), x3.y - bfhi(h3));
            }
        }

        float acc[2][8][4];
        #pragma unroll
        for (int mt = 0; mt < 2; mt++)
            #pragma unroll
            for (int n = 0; n < 8; n++)
                acc[mt][n][0]=acc[mt][n][1]=acc[mt][n][2]=acc[mt][n][3]=0.f;
        float lsum[2][2] = {{0.f,0.f},{0.f,0.f}};

        for (int kt = 0; kt < L_/KT; kt++) {
            int buf = kt & 1, nbuf = buf ^ 1;
            if (kt < L_/KT - 1) {
                int tok = tokbase + (kt+1)*KT;
                {
                    int key = (t & 127) >> 2, c4 = t & 3;
                    if (t < 128)
                        cp16(sb + (AOFF_KH + nbuf*32*PKP + key*PKP + c4*4)*4,
                             KH + (tok + key)*16 + c4*4);
                    else
                        cp16(sb + (AOFF_KL + nbuf*32*PKP + key*PKP + c4*4)*4,
                             KL + (tok + key)*16 + c4*4);
                }
                #pragma unroll
                for (int i = 0; i < 8; i++) {
                    int e = i*256 + t; int rv = e >> 6, cv = e & 63;
                    cp16(sb + (AOFF_V + nbuf*32*PVA + rv*PVA + cv*4)*4,
                         V + (tok + rv)*C_ + cv*4);
                }
                CP_COMMIT();
            }
            const uint32_t* sKhb = sKh + buf*32*PKP;
            const uint32_t* sKlb = sKl + buf*32*PKP;
            const uint32_t* sVb  = sVu + buf*32*PVA;

            // ---- scores (bf16x3, k16): 2 m-tiles x 8 keys ----
            float s[2][4];
            s[0][0]=s[0][1]=s[0][2]=s[0][3]=0.f;
            s[1][0]=s[1][1]=s[1][2]=s[1][3]=0.f;
            #pragma unroll
            for (int kb = 0; kb < 2; kb++) {
                int krow = (ch*8 + g)*PKP;
                uint32_t bh0 = sKhb[krow + kb*8 + t4];
                uint32_t bh1 = sKhb[krow + kb*8 + t4 + 4];
                uint32_t bl0 = sKlb[krow + kb*8 + t4];
                uint32_t bl1 = sKlb[krow + kb*8 + t4 + 4];
                mma16(s[0], ql[0][kb], bh0, bh1);
                mma16(s[0], qh[0][kb], bl0, bl1);
                mma16(s[0], qh[0][kb], bh0, bh1);
                mma16(s[1], ql[1][kb], bh0, bh1);
                mma16(s[1], qh[1][kb], bl0, bl1);
                mma16(s[1], qh[1][kb], bh0, bh1);
            }
            #pragma unroll
            for (int mt = 0; mt < 2; mt++) {
                int rb = rg*32 + mt*16;
                float p0 = __expf(s[mt][0]*SC);
                float p1 = __expf(s[mt][1]*SC);
                float p2 = __expf(s[mt][2]*SC);
                float p3 = __expf(s[mt][3]*SC);
                lsum[mt][0] += p0 + p1;
                lsum[mt][1] += p2 + p3;
                *(float2*)&sPf[(rb + g    )*PP + ch*8 + 2*t4] = make_float2(p0, p1);
                *(float2*)&sPf[(rb + g + 8)*PP + ch*8 + 2*t4] = make_float2(p2, p3);
            }
            __syncthreads();

            // ---- P*V (tf32, raw-fed): 2 m-tiles x 64 cols ----
            #pragma unroll
            for (int kk = 0; kk < 4; kk++) {
                uint32_t a[2][4];
                #pragma unroll
                for (int mt = 0; mt < 2; mt++) {
                    int rb = rg*32 + mt*16;
                    a[mt][0] = sPu[(rb + g    )*PP + kk*8 + t4];
                    a[mt][1] = sPu[(rb + g + 8)*PP + kk*8 + t4];
                    a[mt][2] = sPu[(rb + g    )*PP + kk*8 + t4 + 4];
                    a[mt][3] = sPu[(rb + g + 8)*PP + kk*8 + t4 + 4];
                }
                #pragma unroll
                for (int n = 0; n < 8; n++) {
                    int col = ch*64 + n*8 + g;
                    uint32_t b0 = sVb[(kk*8 + t4    )*PVA + col];
                    uint32_t b1 = sVb[(kk*8 + t4 + 4)*PVA + col];
                    mma8(acc[0][n], a[0], b0, b1);
                    mma8(acc[1][n], a[1], b0, b1);
                }
            }
            if (kt < L_/KT - 1) {
                CP_WAIT0();
            }
            __syncthreads();   // next K/V ready AND sP consumed before rewrite
        }

        // ---- softmax denominators ----
        #pragma unroll
        for (int mt = 0; mt < 2; mt++) {
            #pragma unroll
            for (int j = 0; j < 2; j++) {
                float v = lsum[mt][j];
                v += __shfl_xor_sync(0xffffffffu, v, 1);
                v += __shfl_xor_sync(0xffffffffu, v, 2);
                lsum[mt][j] = v;
            }
        }
        if (t4 == 0) {
            #pragma unroll
            for (int mt = 0; mt < 2; mt++) {
                int rb = rg*32 + mt*16;
                sS[ch*64 + rb + g    ] = lsum[mt][0];
                sS[ch*64 + rb + g + 8] = lsum[mt][1];
            }
        }
        __syncthreads();
        float inv[2][2];
        #pragma unroll
        for (int mt = 0; mt < 2; mt++) {
            int rb = rg*32 + mt*16;
            float d0 = 0.f, d1 = 0.f;
            #pragma unroll
            for (int c = 0; c < 4; c++) {
                d0 += sS[c*64 + rb + g    ];
                d1 += sS[c*64 + rb + g + 8];
            }
            inv[mt][0] = 1.0f / d0;
            inv[mt][1] = 1.0f / d1;
        }

        if (pass == 0) {
            float* st = g_o[h];
            #pragma unroll
            for (int mt = 0; mt < 2; mt++) {
                int r0 = tokbase + row0 + rg*32 + mt*16 + g;
                #pragma unroll
                for (int n = 0; n < 8; n++) {
                    int col = ch*64 + n*8 + 2*t4;
                    *(float2*)&st[ r0     *256 + col] =
                        make_float2(acc[mt][n][0]*inv[mt][0], acc[mt][n][1]*inv[mt][0]);
                    *(float2*)&st[(r0 + 8)*256 + col] =
                        make_float2(acc[mt][n][2]*inv[mt][1], acc[mt][n][3]*inv[mt][1]);
                }
            }
        } else {
            float cf = coefp[0];
            const float* st = g_o[h];
            int ooff = h * 256;
            #pragma unroll
            for (int mt = 0; mt < 2; mt++) {
                int r0 = tokbase + row0 + rg*32 + mt*16 + g;
                #pragma unroll
                for (int n = 0; n < 8; n++) {
                    int col = ch*64 + n*8 + 2*t4;
                    float2 s0 = *(const float2*)&st[ r0     *256 + col];
                    float2 s1 = *(const float2*)&st[(r0 + 8)*256 + col];
                    float2 o0 = make_float2(acc[mt][n][0]*inv[mt][0] + cf*s0.x,
                                            acc[mt][n][1]*inv[mt][0] + cf*s0.y);
                    float2 o1 = make_float2(acc[mt][n][2]*inv[mt][1] + cf*s1.x,
                                            acc[mt][n][3]*inv[mt][1] + cf*s1.y);
                    *(float2*)&dst[ r0     *512 + ooff + col] = o0;
                    *(float2*)&dst[(r0 + 8)*512 + ooff + col] = o1;
                }
            }
        }
    }
}

extern "C" void kernel_launch(void* const* d_in, const int* in_sizes, int n_in,
                              void* d_out, int out_size) {
    const float* x = (const float*)d_in[0];
    const float* wt[12];
    for (int i = 0; i < 12; i++) wt[i] = (const float*)d_in[1+i];
    const float* alpha = (const float*)d_in[13];
    const float* gamma = (const float*)d_in[14];
    float* out = (float*)d_out;

    cudaFuncSetAttribute(proj_qk,
                         cudaFuncAttributeMaxDynamicSharedMemorySize, PROJ_SMEM);
    cudaFuncSetAttribute(proj_v,
                         cudaFuncAttributeMaxDynamicSharedMemorySize, PROJ_SMEM);
    cudaFuncSetAttribute(attn_mma,
                         cudaFuncAttributeMaxDynamicSharedMemorySize, ATTN_SMEM);

    split_kernel<<<2048, 256>>>((const float2*)x, NTOK*C_);

    // y0: X=ecg  wa=w1->q0   wb=w2->k0
    // y1: X=ecg  wa=w4->q1   wb=w11->k3
    // y2: X=pcg  wa=w7->q2   wb=w5->k1
    // y3: X=pcg  wa=w8->k2   wb=w10->q3
    QKArgs qk;
    qk.wa[0] = wt[0];  qk.wb[0] = wt[1];
    qk.wa[1] = wt[3];  qk.wb[1] = wt[10];
    qk.wa[2] = wt[6];  qk.wb[2] = wt[4];
    qk.wa[3] = wt[7];  qk.wb[3] = wt[9];
    proj_qk<<<dim3(NTOK/128, 4), 256, PROJ_SMEM>>>(qk);

    VArgs va;
    va.wv[0] = wt[2]; va.wv[1] = wt[5]; va.wv[2] = wt[8]; va.wv[3] = wt[11];
    proj_v<<<dim3(NTOK/128, 4, 4), 256, PROJ_SMEM>>>(va);

    dim3 ag(L_/ROWS, B_, 2);
    attn_mma<<<ag, 256, ATTN_SMEM>>>(out, alpha, gamma);
}